// round 8
// baseline (speedup 1.0000x reference)
#include <cuda_runtime.h>
#include <math.h>
#include <stdint.h>

#define NN 50000
#define NE 400000
#define D_IN 32
#define D_H 128
#define D_EF 8
#define N_L 2
#define D_OUT 16
#define PC 640
#define NT64 ((NN + 63) / 64)
#define LN_EPS 1e-5f

#define NBINS (2 * NN)            // (type, dst) bins
#define NBPAD (98 * 1024)         // padded to 98 scan blocks

// ------------------------- scratch (device globals) -------------------------
__device__ float g_x[NN * D_H];
__device__ float g_aggr[NN * D_H];
__device__ float g_P[NN * PC];
__device__ float g_WpackT[N_L][5][128 * 128]; // [l][ch][n*128 + k]
__device__ float g_W2T[N_L][2][128 * 128];    // [l][t][n*128 + k]
__device__ float g_WuT[N_L][128 * 256];       // [l][n*256 + k]
__device__ float g_Wf[N_L][2][D_EF * D_H];
__device__ float g_bf[N_L][2][D_H];
__device__ int   g_perm[NE];
__device__ int   g_bins[NBPAD];
__device__ int   g_bsum[98];
__device__ float g_pool[D_H];

// ------------------------- tf32 mma helpers ----------------------------------
__device__ __forceinline__ float f2tf32(float f) {
    uint32_t u;
    asm("cvt.rna.tf32.f32 %0, %1;" : "=r"(u) : "f"(f));
    return __uint_as_float(u);
}
__device__ __forceinline__ void mma8(float* c, const uint32_t* a, uint32_t b0, uint32_t b1) {
    asm volatile(
        "mma.sync.aligned.m16n8k8.row.col.f32.tf32.tf32.f32 "
        "{%0,%1,%2,%3}, {%4,%5,%6,%7}, {%8,%9}, {%0,%1,%2,%3};"
        : "+f"(c[0]), "+f"(c[1]), "+f"(c[2]), "+f"(c[3])
        : "r"(a[0]), "r"(a[1]), "r"(a[2]), "r"(a[3]), "r"(b0), "r"(b1));
}
__device__ __forceinline__ void red2(float* p, float x, float y) {
    asm volatile("red.global.add.v2.f32 [%0], {%1,%2};"
                 :: "l"(p), "f"(x), "f"(y) : "memory");
}

// ------------------------- sort kernels: counting sort by (type, dst) --------
__global__ void k_hist(const int* __restrict__ edge_index,
                       const int* __restrict__ edge_type) {
    int e = blockIdx.x * blockDim.x + threadIdx.x;
    if (e >= NE) return;
    int bin = edge_type[e] * NN + edge_index[NE + e];
    atomicAdd(&g_bins[bin], 1);
}

// 98 blocks x 256 threads; each thread scans 4 consecutive elements.
__global__ void k_scan_local() {
    __shared__ int sT[256];
    int blk = blockIdx.x, tid = threadIdx.x;
    int base = blk * 1024 + tid * 4;
    int c0 = g_bins[base], c1 = g_bins[base + 1], c2 = g_bins[base + 2], c3 = g_bins[base + 3];
    int tot = c0 + c1 + c2 + c3;
    sT[tid] = tot;
    __syncthreads();
    // inclusive scan over 256 thread totals (Hillis-Steele)
    int v = tot;
#pragma unroll
    for (int d = 1; d < 256; d <<= 1) {
        int u = (tid >= d) ? sT[tid - d] : 0;
        __syncthreads();
        v += u;
        sT[tid] = v;
        __syncthreads();
    }
    int excl = v - tot;  // exclusive prefix for this thread within block
    g_bins[base] = excl;
    g_bins[base + 1] = excl + c0;
    g_bins[base + 2] = excl + c0 + c1;
    g_bins[base + 3] = excl + c0 + c1 + c2;
    if (tid == 255) g_bsum[blk] = v;  // block total
}

__global__ void k_scan_top() {
    __shared__ int s[98];
    int tid = threadIdx.x; // 128
    if (tid < 98) s[tid] = g_bsum[tid];
    __syncthreads();
    if (tid == 0) {
        int run = 0;
        for (int i = 0; i < 98; i++) {
            int c = s[i];
            s[i] = run;
            run += c;
        }
    }
    __syncthreads();
    if (tid < 98) g_bsum[tid] = s[tid];
}

__global__ void k_scan_add() {
    int blk = blockIdx.x, tid = threadIdx.x;
    int off = g_bsum[blk];
    int base = blk * 1024 + tid * 4;
    g_bins[base] += off;
    g_bins[base + 1] += off;
    g_bins[base + 2] += off;
    g_bins[base + 3] += off;
}

__global__ void k_scatter(const int* __restrict__ edge_index,
                          const int* __restrict__ edge_type) {
    int e = blockIdx.x * blockDim.x + threadIdx.x;
    if (e >= NE) return;
    int bin = edge_type[e] * NN + edge_index[NE + e];
    int pos = atomicAdd(&g_bins[bin], 1);
    g_perm[pos] = e;
}

// ------------------------- k_setup: zero + fold + packs ----------------------
__global__ void __launch_bounds__(256) k_setup(
    float* out, const float* beam, const float* ris,
    const float* __restrict__ W_leg1, const float* __restrict__ b_leg1,
    const float* __restrict__ W_eav1, const float* __restrict__ b_eav1,
    const float* __restrict__ W_edge, const float* __restrict__ b_edge,
    const float* __restrict__ W_att1,
    const float* __restrict__ W_leg2, const float* __restrict__ W_eav2,
    const float* __restrict__ W_upd) {
    int b = blockIdx.x, tid = threadIdx.x;
    if (b == 0) {
        if (tid < D_H) g_pool[tid] = 0.f;
        if (tid < 64) out[tid] = beam[tid];
        else if (tid < 164) out[tid] = ris[tid - 64];
        return;
    }
    if (b <= 4) {
        __shared__ float sW[64 * D_H];
        __shared__ float sWe[D_EF * D_H];
        __shared__ float sbe[D_H];
        int l = (b - 1) >> 1, t = (b - 1) & 1;
        const float* W1 = (t ? W_eav1 : W_leg1) + l * 384 * D_H;
        const float* b1 = (t ? b_eav1 : b_leg1) + l * D_H;
        for (int idx = tid; idx < D_EF * D_H; idx += 256) sWe[idx] = W_edge[idx];
        if (tid < D_H) sbe[tid] = b_edge[tid];
        float accb = (tid < D_H) ? b1[tid] : 0.f;
        float accj[D_EF];
#pragma unroll
        for (int j = 0; j < D_EF; j++) accj[j] = 0.f;
        for (int cb = 0; cb < 2; cb++) {
            __syncthreads();
            for (int idx = tid; idx < 64 * D_H; idx += 256)
                sW[idx] = W1[(256 + cb * 64 + (idx >> 7)) * D_H + (idx & 127)];
            __syncthreads();
            if (tid < D_H) {
                for (int c2 = 0; c2 < 64; c2++) {
                    float w = sW[c2 * D_H + tid];
                    int c = cb * 64 + c2;
                    accb = fmaf(sbe[c], w, accb);
#pragma unroll
                    for (int j = 0; j < D_EF; j++) accj[j] = fmaf(sWe[j * D_H + c], w, accj[j]);
                }
            }
        }
        if (tid < D_H) {
            g_bf[l][t][tid] = accb;
#pragma unroll
            for (int j = 0; j < D_EF; j++) g_Wf[l][t][j * D_H + tid] = accj[j];
        }
        return;
    }
    if (b <= 14) {
        int l = (b - 5) / 5, ch = (b - 5) % 5;
        for (int idx = tid; idx < 128 * 128; idx += 256) {
            int k = idx >> 7, n = idx & 127;
            float v;
            if (ch < 4) {
                const float* W1 = ((ch >> 1) ? W_eav1 : W_leg1) + l * 384 * D_H;
                v = W1[((ch & 1) * 128 + k) * D_H + n];
            } else {
                const float* Wa = W_att1 + l * 256 * 64;
                v = (n < 64) ? Wa[k * 64 + n] : Wa[(128 + k) * 64 + (n - 64)];
            }
            g_WpackT[l][ch][n * 128 + k] = v;
        }
        return;
    }
    if (b <= 18) {
        int l = (b - 15) >> 1, t = (b - 15) & 1;
        const float* W2 = (t ? W_eav2 : W_leg2) + l * D_H * D_H;
        for (int idx = tid; idx < 128 * 128; idx += 256) {
            int n = idx >> 7, k = idx & 127;
            g_W2T[l][t][n * 128 + k] = W2[k * D_H + n];
        }
        return;
    }
    {
        int l = b - 19;
        const float* Wu = W_upd + l * 256 * D_H;
        for (int idx = tid; idx < 128 * 256; idx += 256) {
            int n = idx >> 8, k = idx & 255;
            g_WuT[l][n * 256 + k] = Wu[k * D_H + n];
        }
    }
}

// ------------------------- k_embed: x = x_in @ W_node + b --------------------
__global__ void __launch_bounds__(256) k_embed(const float* __restrict__ x_in,
                                               const float* __restrict__ W_node,
                                               const float* __restrict__ b_node) {
    __shared__ float sA[64][D_IN + 1];
    __shared__ __align__(16) float sB[D_IN * D_H];
    __shared__ float sb[D_H];
    int tid = threadIdx.x;
    int row0 = blockIdx.x * 64;
    for (int idx = tid; idx < 64 * D_IN; idx += 256) {
        int i = idx >> 5, c = idx & 31;
        int r = row0 + i;
        sA[i][c] = (r < NN) ? x_in[r * D_IN + c] : 0.f;
    }
    for (int idx = tid; idx < D_IN * D_H; idx += 256) sB[idx] = W_node[idx];
    if (tid < D_H) sb[tid] = b_node[tid];
    __syncthreads();
    int tx = tid & 15, ty = tid >> 4;
    float acc[4][8];
#pragma unroll
    for (int r = 0; r < 4; r++)
#pragma unroll
        for (int j = 0; j < 8; j++) acc[r][j] = 0.f;
    for (int c = 0; c < D_IN; c++) {
        float a[4];
#pragma unroll
        for (int r = 0; r < 4; r++) a[r] = sA[ty * 4 + r][c];
        float4 b0 = *(const float4*)(sB + c * D_H + tx * 8);
        float4 b1 = *(const float4*)(sB + c * D_H + tx * 8 + 4);
        float bb[8] = {b0.x, b0.y, b0.z, b0.w, b1.x, b1.y, b1.z, b1.w};
#pragma unroll
        for (int r = 0; r < 4; r++)
#pragma unroll
            for (int j = 0; j < 8; j++) acc[r][j] = fmaf(a[r], bb[j], acc[r][j]);
    }
#pragma unroll
    for (int r = 0; r < 4; r++) {
        int row = row0 + ty * 4 + r;
        if (row < NN) {
#pragma unroll
            for (int j = 0; j < 8; j++) {
                int col = tx * 8 + j;
                g_x[row * D_H + col] = acc[r][j] + sb[col];
            }
        }
    }
}

// ------------------------- k_proj_mma: 64-row tiles, 4 blocks/SM -------------
#define SMEM_PROJ ((64 * 68 + 128 * 68) * 4)
__global__ void __launch_bounds__(256, 4) k_proj_mma(int l) {
    extern __shared__ __align__(16) float sm[];
    float* sA = sm;              // 64 x 68
    float* sB = sm + 64 * 68;    // 128 x 68
    int tid = threadIdx.x;
    int row0 = blockIdx.x * 64;
    int ch = blockIdx.y;
    int wid = tid >> 5, lane = tid & 31;
    int wy = wid >> 2, wx = wid & 3;
    int g = lane >> 2, tig = lane & 3;
    const float* WT = g_WpackT[l][ch];
    float c[2][4][4];
#pragma unroll
    for (int mt = 0; mt < 2; mt++)
#pragma unroll
        for (int nt = 0; nt < 4; nt++)
#pragma unroll
            for (int j = 0; j < 4; j++) c[mt][nt][j] = 0.f;
    for (int chunk = 0; chunk < 2; chunk++) {
        __syncthreads();
        for (int idx = tid; idx < 64 * 16; idx += 256) {
            int m = idx >> 4, q4 = (idx & 15) * 4;
            int r = row0 + m;
            float4 v = make_float4(0.f, 0.f, 0.f, 0.f);
            if (r < NN) v = *(const float4*)(g_x + r * D_H + chunk * 64 + q4);
            v.x = f2tf32(v.x); v.y = f2tf32(v.y); v.z = f2tf32(v.z); v.w = f2tf32(v.w);
            *(float4*)(sA + m * 68 + q4) = v;
        }
        for (int idx = tid; idx < 128 * 16; idx += 256) {
            int n = idx >> 4, q4 = (idx & 15) * 4;
            float4 v = *(const float4*)(WT + n * 128 + chunk * 64 + q4);
            v.x = f2tf32(v.x); v.y = f2tf32(v.y); v.z = f2tf32(v.z); v.w = f2tf32(v.w);
            *(float4*)(sB + n * 68 + q4) = v;
        }
        __syncthreads();
#pragma unroll
        for (int ks = 0; ks < 8; ks++) {
            int ka = ks * 8 + tig;
            uint32_t a[2][4];
#pragma unroll
            for (int mt = 0; mt < 2; mt++) {
                int base = wy * 32 + mt * 16;
                a[mt][0] = __float_as_uint(sA[(base + g) * 68 + ka]);
                a[mt][1] = __float_as_uint(sA[(base + g + 8) * 68 + ka]);
                a[mt][2] = __float_as_uint(sA[(base + g) * 68 + ka + 4]);
                a[mt][3] = __float_as_uint(sA[(base + g + 8) * 68 + ka + 4]);
            }
#pragma unroll
            for (int nt = 0; nt < 4; nt++) {
                int nb = wx * 32 + nt * 8 + g;
                uint32_t b0 = __float_as_uint(sB[nb * 68 + ka]);
                uint32_t b1 = __float_as_uint(sB[nb * 68 + ka + 4]);
                mma8(c[0][nt], a[0], b0, b1);
                mma8(c[1][nt], a[1], b0, b1);
            }
        }
    }
#pragma unroll
    for (int mt = 0; mt < 2; mt++) {
        int r0 = row0 + wy * 32 + mt * 16 + g;
#pragma unroll
        for (int nt = 0; nt < 4; nt++) {
            int col = ch * 128 + wx * 32 + nt * 8 + 2 * tig;
            if (r0 < NN)
                *(float2*)(g_P + (size_t)r0 * PC + col) = make_float2(c[mt][nt][0], c[mt][nt][1]);
            if (r0 + 8 < NN)
                *(float2*)(g_P + (size_t)(r0 + 8) * PC + col) = make_float2(c[mt][nt][2], c[mt][nt][3]);
        }
    }
}

// ------------------------- k_edge: 64-edge tiles (dst-sorted), 3 blocks/SM ---
#define SMEM_EDGE 60416
__global__ void __launch_bounds__(256, 3) k_edge(
    int l, const int* __restrict__ edge_index, const int* __restrict__ edge_type,
    const float* __restrict__ edge_attr,
    const float* __restrict__ b_leg2, const float* __restrict__ b_eav2,
    const float* __restrict__ W_att2, const float* __restrict__ b_att2,
    const float* __restrict__ b_att1) {
    extern __shared__ __align__(16) char smraw[];
    int* s_dst = (int*)smraw;
    int* s_src = (int*)(smraw + 256);
    int* s_et  = (int*)(smraw + 512);
    float* s_att = (float*)(smraw + 768);
    float* s_ea  = (float*)(smraw + 1024);
    float* s_Wf  = (float*)(smraw + 3072);
    float* s_bf  = (float*)(smraw + 7168);
    float* s_ba1 = (float*)(smraw + 7680);
    float* s_wa2 = (float*)(smraw + 7936);
    float* s_hid = (float*)(smraw + 8192);   // 64 x 132
    float* s_B   = (float*)(smraw + 41984);  // 128 x 36
    float* s_atth = s_hid;                   // gate scratch 64x68 overlay
    __shared__ int sh_np, sh_t0;

    int tid = threadIdx.x;
    int tile0 = blockIdx.x * 64;
    if (tid < 64) {
        int e = g_perm[tile0 + tid];
        s_src[tid] = edge_index[e];
        s_dst[tid] = edge_index[NE + e];
        s_et[tid]  = edge_type[e];
#pragma unroll
        for (int j = 0; j < D_EF; j++) s_ea[tid * D_EF + j] = edge_attr[e * D_EF + j];
    } else if (tid < 128) {
        s_ba1[tid - 64] = b_att1[l * 64 + (tid - 64)];
    } else if (tid < 192) {
        s_wa2[tid - 128] = W_att2[l * 64 + (tid - 128)];
    }
    __syncthreads();
    if (tid == 0) {
        int t0 = s_et[0];
        sh_t0 = t0;
        sh_np = (s_et[63] == t0) ? 1 : 2;
    }
    __syncthreads();
    int npasses = sh_np;
    float ba2 = b_att2[l];
    int wid = tid >> 5, lane = tid & 31;
    int wy = wid >> 2, wx = wid & 3;
    int g = lane >> 2, tig = lane & 3;

    for (int p = 0; p < npasses; p++) {
        int t = (npasses == 1) ? sh_t0 : p;
        for (int idx = tid; idx < D_EF * D_H; idx += 256) s_Wf[idx] = g_Wf[l][t][idx];
        if (tid < D_H) s_bf[tid] = g_bf[l][t][tid];
        if (t == 1) {
            for (int idx = tid; idx < 64 * 64; idx += 256) {
                int i = idx >> 6, m = idx & 63;
                int d = s_dst[i], s = s_src[i];
                float v = __ldg(g_P + (size_t)d * PC + 512 + m) +
                          __ldg(g_P + (size_t)s * PC + 576 + m) + s_ba1[m];
                s_atth[m * 68 + i] = fmaxf(v, 0.f);
            }
            __syncthreads();
            if (tid < 64) {
                float z = ba2;
#pragma unroll 8
                for (int m = 0; m < 64; m++) z = fmaf(s_atth[m * 68 + tid], s_wa2[m], z);
                s_att[tid] = 1.f / (1.f + expf(-z));
            }
        }
        __syncthreads();
        // phase1: hidden = relu(P_dst + P_src + ea@Wf + bf)
        {
            int q = tid & 31, gi = tid >> 5;
            int k4 = q * 4;
            int cD = t ? 256 : 0;
            float4 bf4 = *(const float4*)(s_bf + k4);
#pragma unroll 2
            for (int i = gi; i < 64; i += 8) {
                int d = s_dst[i], s = s_src[i];
                float4 vd = __ldg((const float4*)(g_P + (size_t)d * PC + cD + k4));
                float4 vs = __ldg((const float4*)(g_P + (size_t)s * PC + cD + 128 + k4));
                float a0 = bf4.x + vd.x + vs.x;
                float a1 = bf4.y + vd.y + vs.y;
                float a2v = bf4.z + vd.z + vs.z;
                float a3 = bf4.w + vd.w + vs.w;
#pragma unroll
                for (int j = 0; j < D_EF; j++) {
                    float e = s_ea[i * D_EF + j];
                    float4 w = *(const float4*)(s_Wf + j * D_H + k4);
                    a0 = fmaf(e, w.x, a0); a1 = fmaf(e, w.y, a1);
                    a2v = fmaf(e, w.z, a2v); a3 = fmaf(e, w.w, a3);
                }
                float* hp = s_hid + i * 132 + k4;
                *(float2*)hp = make_float2(f2tf32(fmaxf(a0, 0.f)), f2tf32(fmaxf(a1, 0.f)));
                *(float2*)(hp + 2) = make_float2(f2tf32(fmaxf(a2v, 0.f)), f2tf32(fmaxf(a3, 0.f)));
            }
        }
        // GEMM2: 64x128x128 via tf32 mma, 32-K B chunks
        const float* W2T = g_W2T[l][t];
        const float* b2 = (t ? b_eav2 : b_leg2) + l * D_H;
        float c[2][4][4];
#pragma unroll
        for (int mt = 0; mt < 2; mt++)
#pragma unroll
            for (int nt = 0; nt < 4; nt++)
#pragma unroll
                for (int j = 0; j < 4; j++) c[mt][nt][j] = 0.f;
        for (int chunk = 0; chunk < 4; chunk++) {
            __syncthreads();
            for (int idx = tid; idx < 128 * 8; idx += 256) {
                int n = idx >> 3, q4 = (idx & 7) * 4;
                float4 v = *(const float4*)(W2T + n * 128 + chunk * 32 + q4);
                v.x = f2tf32(v.x); v.y = f2tf32(v.y); v.z = f2tf32(v.z); v.w = f2tf32(v.w);
                *(float4*)(s_B + n * 36 + q4) = v;
            }
            __syncthreads();
#pragma unroll
            for (int ks = 0; ks < 4; ks++) {
                int kh = chunk * 32 + ks * 8 + tig;
                int kb = ks * 8 + tig;
                uint32_t a[2][4];
#pragma unroll
                for (int mt = 0; mt < 2; mt++) {
                    int base = wy * 32 + mt * 16;
                    a[mt][0] = __float_as_uint(s_hid[(base + g) * 132 + kh]);
                    a[mt][1] = __float_as_uint(s_hid[(base + g + 8) * 132 + kh]);
                    a[mt][2] = __float_as_uint(s_hid[(base + g) * 132 + kh + 4]);
                    a[mt][3] = __float_as_uint(s_hid[(base + g + 8) * 132 + kh + 4]);
                }
#pragma unroll
                for (int nt = 0; nt < 4; nt++) {
                    int nb = wx * 32 + nt * 8 + g;
                    uint32_t b0 = __float_as_uint(s_B[nb * 36 + kb]);
                    uint32_t b1 = __float_as_uint(s_B[nb * 36 + kb + 4]);
                    mma8(c[0][nt], a[0], b0, b1);
                    mma8(c[1][nt], a[1], b0, b1);
                }
            }
        }
        // epilogue: bias + gate + scatter
#pragma unroll
        for (int mt = 0; mt < 2; mt++) {
            int i0 = wy * 32 + mt * 16 + g;
            int i1 = i0 + 8;
            bool p0 = (npasses == 1) || (s_et[i0] == t);
            bool p1 = (npasses == 1) || (s_et[i1] == t);
            float sc0 = t ? s_att[i0] : 1.f;
            float sc1 = t ? s_att[i1] : 1.f;
            int d0 = s_dst[i0], d1 = s_dst[i1];
#pragma unroll
            for (int nt = 0; nt < 4; nt++) {
                int col = wx * 32 + nt * 8 + 2 * tig;
                float2 bv = *(const float2*)(b2 + col);
                if (p0) red2(g_aggr + (size_t)d0 * D_H + col,
                             (c[mt][nt][0] + bv.x) * sc0, (c[mt][nt][1] + bv.y) * sc0);
                if (p1) red2(g_aggr + (size_t)d1 * D_H + col,
                             (c[mt][nt][2] + bv.x) * sc1, (c[mt][nt][3] + bv.y) * sc1);
            }
        }
        __syncthreads();
    }
}

// ------------------------- k_update_mma: mma + LN + residual -----------------
#define SMEM_UPD ((64 * 68 + 128 * 68 + 128 * 3 + 64 * 4 * 2 + 128) * 4)
__global__ void __launch_bounds__(256, 4) k_update_mma(
    int l, const float* __restrict__ b_upd,
    const float* __restrict__ ln_g, const float* __restrict__ ln_b) {
    extern __shared__ __align__(16) float sm[];
    float* sA = sm;                       // 64 x 68
    float* sB = sA + 64 * 68;             // 128 x 68
    float* sBias = sB + 128 * 68;         // 128
    float* sGam = sBias + 128;            // 128
    float* sBet = sGam + 128;             // 128
    float* sP1 = sBet + 128;              // 64 x 4
    float* sP2 = sP1 + 256;               // 64 x 4
    float* sMu = sP2 + 256;               // 64
    float* sRs = sMu + 64;                // 64
    int tid = threadIdx.x;
    int row0 = blockIdx.x * 64;
    int wid = tid >> 5, lane = tid & 31;
    int wy = wid >> 2, wx = wid & 3;
    int g = lane >> 2, tig = lane & 3;
    if (tid < 128) {
        sBias[tid] = b_upd[l * D_H + tid];
        sGam[tid] = ln_g[l * D_H + tid];
        sBet[tid] = ln_b[l * D_H + tid];
    }
    const float* WuT = g_WuT[l];
    float c[2][4][4];
#pragma unroll
    for (int mt = 0; mt < 2; mt++)
#pragma unroll
        for (int nt = 0; nt < 4; nt++)
#pragma unroll
            for (int j = 0; j < 4; j++) c[mt][nt][j] = 0.f;
    for (int chunk = 0; chunk < 4; chunk++) {
        __syncthreads();
        const float* Asrc = (chunk < 2) ? g_x : g_aggr;
        int cbase = (chunk & 1) * 64;
        for (int idx = tid; idx < 64 * 16; idx += 256) {
            int m = idx >> 4, q4 = (idx & 15) * 4;
            int r = row0 + m;
            float4 v = make_float4(0.f, 0.f, 0.f, 0.f);
            if (r < NN) v = *(const float4*)(Asrc + r * D_H + cbase + q4);
            v.x = f2tf32(v.x); v.y = f2tf32(v.y); v.z = f2tf32(v.z); v.w = f2tf32(v.w);
            *(float4*)(sA + m * 68 + q4) = v;
        }
        for (int idx = tid; idx < 128 * 16; idx += 256) {
            int n = idx >> 4, q4 = (idx & 15) * 4;
            float4 v = *(const float4*)(WuT + n * 256 + chunk * 64 + q4);
            v.x = f2tf32(v.x); v.y = f2tf32(v.y); v.z = f2tf32(v.z); v.w = f2tf32(v.w);
            *(float4*)(sB + n * 68 + q4) = v;
        }
        __syncthreads();
#pragma unroll
        for (int ks = 0; ks < 8; ks++) {
            int ka = ks * 8 + tig;
            uint32_t a[2][4];
#pragma unroll
            for (int mt = 0; mt < 2; mt++) {
                int base = wy * 32 + mt * 16;
                a[mt][0] = __float_as_uint(sA[(base + g) * 68 + ka]);
                a[mt][1] = __float_as_uint(sA[(base + g + 8) * 68 + ka]);
                a[mt][2] = __float_as_uint(sA[(base + g) * 68 + ka + 4]);
                a[mt][3] = __float_as_uint(sA[(base + g + 8) * 68 + ka + 4]);
            }
#pragma unroll
            for (int nt = 0; nt < 4; nt++) {
                int nb = wx * 32 + nt * 8 + g;
                uint32_t b0 = __float_as_uint(sB[nb * 68 + ka]);
                uint32_t b1 = __float_as_uint(sB[nb * 68 + ka + 4]);
                mma8(c[0][nt], a[0], b0, b1);
                mma8(c[1][nt], a[1], b0, b1);
            }
        }
    }
#pragma unroll
    for (int mt = 0; mt < 2; mt++) {
        float s1a = 0.f, s2a = 0.f, s1b = 0.f, s2b = 0.f;
#pragma unroll
        for (int nt = 0; nt < 4; nt++) {
            int col = wx * 32 + nt * 8 + 2 * tig;
            float b0 = sBias[col], b1 = sBias[col + 1];
            c[mt][nt][0] += b0; c[mt][nt][1] += b1;
            c[mt][nt][2] += b0; c[mt][nt][3] += b1;
            s1a += c[mt][nt][0] + c[mt][nt][1];
            s2a += c[mt][nt][0] * c[mt][nt][0] + c[mt][nt][1] * c[mt][nt][1];
            s1b += c[mt][nt][2] + c[mt][nt][3];
            s2b += c[mt][nt][2] * c[mt][nt][2] + c[mt][nt][3] * c[mt][nt][3];
        }
#pragma unroll
        for (int d = 1; d <= 2; d <<= 1) {
            s1a += __shfl_xor_sync(0xffffffff, s1a, d);
            s2a += __shfl_xor_sync(0xffffffff, s2a, d);
            s1b += __shfl_xor_sync(0xffffffff, s1b, d);
            s2b += __shfl_xor_sync(0xffffffff, s2b, d);
        }
        if (tig == 0) {
            int ra = wy * 32 + mt * 16 + g;
            sP1[ra * 4 + wx] = s1a;
            sP2[ra * 4 + wx] = s2a;
            sP1[(ra + 8) * 4 + wx] = s1b;
            sP2[(ra + 8) * 4 + wx] = s2b;
        }
    }
    __syncthreads();
    if (tid < 64) {
        float s1 = sP1[tid * 4] + sP1[tid * 4 + 1] + sP1[tid * 4 + 2] + sP1[tid * 4 + 3];
        float s2 = sP2[tid * 4] + sP2[tid * 4 + 1] + sP2[tid * 4 + 2] + sP2[tid * 4 + 3];
        float mu = s1 * (1.f / D_H);
        float var = fmaxf(s2 * (1.f / D_H) - mu * mu, 0.f);
        sMu[tid] = mu;
        sRs[tid] = rsqrtf(var + LN_EPS);
    }
    __syncthreads();
#pragma unroll
    for (int mt = 0; mt < 2; mt++) {
        int ra = wy * 32 + mt * 16 + g;
        int rows[2] = {ra, ra + 8};
#pragma unroll
        for (int h = 0; h < 2; h++) {
            int rr = rows[h];
            int grow = row0 + rr;
            if (grow >= NN) continue;
            float mu = sMu[rr], rs = sRs[rr];
#pragma unroll
            for (int nt = 0; nt < 4; nt++) {
                int col = wx * 32 + nt * 8 + 2 * tig;
                float v0 = c[mt][nt][h * 2], v1 = c[mt][nt][h * 2 + 1];
                float2 xo = *(const float2*)(g_x + (size_t)grow * D_H + col);
                float h0 = (v0 - mu) * rs * sGam[col] + sBet[col];
                float h1 = (v1 - mu) * rs * sGam[col + 1] + sBet[col + 1];
                float o0 = fmaxf(fmaxf(h0, 0.f) + xo.x, 0.f);
                float o1 = fmaxf(fmaxf(h1, 0.f) + xo.y, 0.f);
                *(float2*)(g_x + (size_t)grow * D_H + col) = make_float2(o0, o1);
            }
        }
    }
}

// ------------------------- k_pool -------------------------------------------
__global__ void k_pool() {
    __shared__ float sp[256];
    int tid = threadIdx.x;
    int row0 = blockIdx.x * 64;
    int k = tid & 127, ih = tid >> 7;
    float v = 0.f;
    for (int i = ih; i < 64; i += 2) {
        int r = row0 + i;
        if (r < NN) v += g_x[r * D_H + k];
    }
    sp[tid] = v;
    __syncthreads();
    if (tid < 128) atomicAdd(&g_pool[k], sp[tid] + sp[tid + 128]);
}

// ------------------------- k_head -------------------------------------------
__global__ void k_head(float* out, const float* __restrict__ traj,
                       const float* __restrict__ W_ref1, const float* __restrict__ b_ref1,
                       const float* __restrict__ W_ref2, const float* __restrict__ b_ref2) {
    __shared__ float sg[D_H], sr1[D_H];
    int tid = threadIdx.x; // 128
    sg[tid] = g_pool[tid] * (1.f / NN);
    __syncthreads();
    float acc = b_ref1[tid];
    for (int c = 0; c < D_H; c++) acc = fmaf(sg[c], W_ref1[c * D_H + tid], acc);
    sr1[tid] = fmaxf(acc, 0.f);
    __syncthreads();
    if (tid < D_OUT) {
        float r2 = b_ref2[tid];
        for (int c = 0; c < D_H; c++) r2 = fmaf(sr1[c], W_ref2[c * D_OUT + tid], r2);
        if (tid < 3) out[164 + tid] = traj[tid] + r2;
    }
    out[167 + tid] = sg[tid];
}

// ------------------------- launch ------------------------------------------
extern "C" void kernel_launch(void* const* d_in, const int* in_sizes, int n_in,
                              void* d_out, int out_size) {
    const float* x_in      = (const float*)d_in[0];
    const float* edge_attr = (const float*)d_in[1];
    const int*   edge_index= (const int*)d_in[2];
    const int*   edge_type = (const int*)d_in[3];
    const float* beam      = (const float*)d_in[5];
    const float* ris       = (const float*)d_in[6];
    const float* traj      = (const float*)d_in[7];
    const float* W_node = (const float*)d_in[8];
    const float* b_node = (const float*)d_in[9];
    const float* W_edge = (const float*)d_in[10];
    const float* b_edge = (const float*)d_in[11];
    const float* W_leg1 = (const float*)d_in[12];
    const float* b_leg1 = (const float*)d_in[13];
    const float* W_leg2 = (const float*)d_in[14];
    const float* b_leg2 = (const float*)d_in[15];
    const float* W_eav1 = (const float*)d_in[16];
    const float* b_eav1 = (const float*)d_in[17];
    const float* W_eav2 = (const float*)d_in[18];
    const float* b_eav2 = (const float*)d_in[19];
    const float* W_att1 = (const float*)d_in[20];
    const float* b_att1 = (const float*)d_in[21];
    const float* W_att2 = (const float*)d_in[22];
    const float* b_att2 = (const float*)d_in[23];
    const float* W_upd  = (const float*)d_in[24];
    const float* b_upd  = (const float*)d_in[25];
    const float* ln_g   = (const float*)d_in[26];
    const float* ln_b   = (const float*)d_in[27];
    const float* W_ref1 = (const float*)d_in[28];
    const float* b_ref1 = (const float*)d_in[29];
    const float* W_ref2 = (const float*)d_in[30];
    const float* b_ref2 = (const float*)d_in[31];
    float* out = (float*)d_out;

    cudaFuncSetAttribute(k_proj_mma,   cudaFuncAttributeMaxDynamicSharedMemorySize, SMEM_PROJ);
    cudaFuncSetAttribute(k_edge,       cudaFuncAttributeMaxDynamicSharedMemorySize, SMEM_EDGE);
    cudaFuncSetAttribute(k_update_mma, cudaFuncAttributeMaxDynamicSharedMemorySize, SMEM_UPD);

    void* aggr_ptr = nullptr;
    void* bins_ptr = nullptr;
    cudaGetSymbolAddress(&aggr_ptr, g_aggr);
    cudaGetSymbolAddress(&bins_ptr, g_bins);

    // edge sort by (type, dst): histogram -> scan -> scatter
    cudaMemsetAsync(bins_ptr, 0, NBPAD * sizeof(int));
    k_hist<<<(NE + 255) / 256, 256>>>(edge_index, edge_type);
    k_scan_local<<<98, 256>>>();
    k_scan_top<<<1, 128>>>();
    k_scan_add<<<98, 256>>>();
    k_scatter<<<(NE + 255) / 256, 256>>>(edge_index, edge_type);

    k_setup<<<21, 256>>>(out, beam, ris, W_leg1, b_leg1, W_eav1, b_eav1,
                         W_edge, b_edge, W_att1, W_leg2, W_eav2, W_upd);
    k_embed<<<NT64, 256>>>(x_in, W_node, b_node);

    for (int l = 0; l < N_L; l++) {
        cudaMemsetAsync(aggr_ptr, 0, (size_t)NN * D_H * sizeof(float));
        k_proj_mma<<<dim3(NT64, 5), 256, SMEM_PROJ>>>(l);
        k_edge<<<NE / 64, 256, SMEM_EDGE>>>(l, edge_index, edge_type, edge_attr,
                                            b_leg2, b_eav2, W_att2, b_att2, b_att1);
        k_update_mma<<<NT64, 256, SMEM_UPD>>>(l, b_upd, ln_g, ln_b);
    }

    k_pool<<<NT64, 256>>>();
    k_head<<<1, 128>>>(out, traj, W_ref1, b_ref1, W_ref2, b_ref2);
}

// round 9
// speedup vs baseline: 1.0837x; 1.0837x over previous
#include <cuda_runtime.h>
#include <math.h>
#include <stdint.h>

#define NN 50000
#define NE 400000
#define D_IN 32
#define D_H 128
#define D_EF 8
#define N_L 2
#define D_OUT 16
#define PC 640
#define NT64 ((NN + 63) / 64)
#define LN_EPS 1e-5f

#define NBINS (2 * NN)            // (type, dst) bins
#define NBPAD (98 * 1024)         // padded to 98 scan blocks

// ------------------------- scratch (device globals) -------------------------
__device__ float g_x[NN * D_H];
__device__ float g_aggr[NN * D_H];
__device__ float g_P[NN * PC];
__device__ float g_WpackT[N_L][5][128 * 128]; // [l][ch][n*128 + k]
__device__ float g_W2T[N_L][2][128 * 128];    // [l][t][n*128 + k]
__device__ float g_WuT[N_L][128 * 256];       // [l][n*256 + k]
__device__ float g_Wf[N_L][2][D_EF * D_H];
__device__ float g_bf[N_L][2][D_H];
__device__ int   g_perm[NE];
__device__ int   g_bins[NBPAD];
__device__ int   g_bsum[98];
__device__ float g_pool[D_H];

// ------------------------- tf32 mma helpers ----------------------------------
__device__ __forceinline__ float f2tf32(float f) {
    uint32_t u;
    asm("cvt.rna.tf32.f32 %0, %1;" : "=r"(u) : "f"(f));
    return __uint_as_float(u);
}
__device__ __forceinline__ void mma8(float* c, const uint32_t* a, uint32_t b0, uint32_t b1) {
    asm volatile(
        "mma.sync.aligned.m16n8k8.row.col.f32.tf32.tf32.f32 "
        "{%0,%1,%2,%3}, {%4,%5,%6,%7}, {%8,%9}, {%0,%1,%2,%3};"
        : "+f"(c[0]), "+f"(c[1]), "+f"(c[2]), "+f"(c[3])
        : "r"(a[0]), "r"(a[1]), "r"(a[2]), "r"(a[3]), "r"(b0), "r"(b1));
}
__device__ __forceinline__ void red4(float* p, float x, float y, float z, float w) {
    asm volatile("red.global.add.v4.f32 [%0], {%1,%2,%3,%4};"
                 :: "l"(p), "f"(x), "f"(y), "f"(z), "f"(w) : "memory");
}

// ------------------------- sort kernels: counting sort by (type, dst) --------
__global__ void k_hist(const int* __restrict__ edge_index,
                       const int* __restrict__ edge_type) {
    int e = blockIdx.x * blockDim.x + threadIdx.x;
    if (e >= NE) return;
    int bin = edge_type[e] * NN + edge_index[NE + e];
    atomicAdd(&g_bins[bin], 1);
}

__global__ void k_scan_local() {
    __shared__ int sT[256];
    int blk = blockIdx.x, tid = threadIdx.x;
    int base = blk * 1024 + tid * 4;
    int c0 = g_bins[base], c1 = g_bins[base + 1], c2 = g_bins[base + 2], c3 = g_bins[base + 3];
    int tot = c0 + c1 + c2 + c3;
    sT[tid] = tot;
    __syncthreads();
    int v = tot;
#pragma unroll
    for (int d = 1; d < 256; d <<= 1) {
        int u = (tid >= d) ? sT[tid - d] : 0;
        __syncthreads();
        v += u;
        sT[tid] = v;
        __syncthreads();
    }
    int excl = v - tot;
    g_bins[base] = excl;
    g_bins[base + 1] = excl + c0;
    g_bins[base + 2] = excl + c0 + c1;
    g_bins[base + 3] = excl + c0 + c1 + c2;
    if (tid == 255) g_bsum[blk] = v;
}

__global__ void k_scan_top() {
    __shared__ int s[98];
    int tid = threadIdx.x; // 128
    if (tid < 98) s[tid] = g_bsum[tid];
    __syncthreads();
    if (tid == 0) {
        int run = 0;
        for (int i = 0; i < 98; i++) {
            int c = s[i];
            s[i] = run;
            run += c;
        }
    }
    __syncthreads();
    if (tid < 98) g_bsum[tid] = s[tid];
}

__global__ void k_scan_add() {
    int blk = blockIdx.x, tid = threadIdx.x;
    int off = g_bsum[blk];
    int base = blk * 1024 + tid * 4;
    g_bins[base] += off;
    g_bins[base + 1] += off;
    g_bins[base + 2] += off;
    g_bins[base + 3] += off;
}

__global__ void k_scatter(const int* __restrict__ edge_index,
                          const int* __restrict__ edge_type) {
    int e = blockIdx.x * blockDim.x + threadIdx.x;
    if (e >= NE) return;
    int bin = edge_type[e] * NN + edge_index[NE + e];
    int pos = atomicAdd(&g_bins[bin], 1);
    g_perm[pos] = e;
}

// ------------------------- k_setup: zero + fold + packs ----------------------
__global__ void __launch_bounds__(256) k_setup(
    float* out, const float* beam, const float* ris,
    const float* __restrict__ W_leg1, const float* __restrict__ b_leg1,
    const float* __restrict__ W_eav1, const float* __restrict__ b_eav1,
    const float* __restrict__ W_edge, const float* __restrict__ b_edge,
    const float* __restrict__ W_att1,
    const float* __restrict__ W_leg2, const float* __restrict__ W_eav2,
    const float* __restrict__ W_upd) {
    int b = blockIdx.x, tid = threadIdx.x;
    if (b == 0) {
        if (tid < D_H) g_pool[tid] = 0.f;
        if (tid < 64) out[tid] = beam[tid];
        else if (tid < 164) out[tid] = ris[tid - 64];
        return;
    }
    if (b <= 4) {
        __shared__ float sW[64 * D_H];
        __shared__ float sWe[D_EF * D_H];
        __shared__ float sbe[D_H];
        int l = (b - 1) >> 1, t = (b - 1) & 1;
        const float* W1 = (t ? W_eav1 : W_leg1) + l * 384 * D_H;
        const float* b1 = (t ? b_eav1 : b_leg1) + l * D_H;
        for (int idx = tid; idx < D_EF * D_H; idx += 256) sWe[idx] = W_edge[idx];
        if (tid < D_H) sbe[tid] = b_edge[tid];
        float accb = (tid < D_H) ? b1[tid] : 0.f;
        float accj[D_EF];
#pragma unroll
        for (int j = 0; j < D_EF; j++) accj[j] = 0.f;
        for (int cb = 0; cb < 2; cb++) {
            __syncthreads();
            for (int idx = tid; idx < 64 * D_H; idx += 256)
                sW[idx] = W1[(256 + cb * 64 + (idx >> 7)) * D_H + (idx & 127)];
            __syncthreads();
            if (tid < D_H) {
                for (int c2 = 0; c2 < 64; c2++) {
                    float w = sW[c2 * D_H + tid];
                    int c = cb * 64 + c2;
                    accb = fmaf(sbe[c], w, accb);
#pragma unroll
                    for (int j = 0; j < D_EF; j++) accj[j] = fmaf(sWe[j * D_H + c], w, accj[j]);
                }
            }
        }
        if (tid < D_H) {
            g_bf[l][t][tid] = accb;
#pragma unroll
            for (int j = 0; j < D_EF; j++) g_Wf[l][t][j * D_H + tid] = accj[j];
        }
        return;
    }
    if (b <= 14) {
        int l = (b - 5) / 5, ch = (b - 5) % 5;
        for (int idx = tid; idx < 128 * 128; idx += 256) {
            int k = idx >> 7, n = idx & 127;
            float v;
            if (ch < 4) {
                const float* W1 = ((ch >> 1) ? W_eav1 : W_leg1) + l * 384 * D_H;
                v = W1[((ch & 1) * 128 + k) * D_H + n];
            } else {
                const float* Wa = W_att1 + l * 256 * 64;
                v = (n < 64) ? Wa[k * 64 + n] : Wa[(128 + k) * 64 + (n - 64)];
            }
            g_WpackT[l][ch][n * 128 + k] = v;
        }
        return;
    }
    if (b <= 18) {
        int l = (b - 15) >> 1, t = (b - 15) & 1;
        const float* W2 = (t ? W_eav2 : W_leg2) + l * D_H * D_H;
        for (int idx = tid; idx < 128 * 128; idx += 256) {
            int n = idx >> 7, k = idx & 127;
            g_W2T[l][t][n * 128 + k] = W2[k * D_H + n];
        }
        return;
    }
    {
        int l = b - 19;
        const float* Wu = W_upd + l * 256 * D_H;
        for (int idx = tid; idx < 128 * 256; idx += 256) {
            int n = idx >> 8, k = idx & 255;
            g_WuT[l][n * 256 + k] = Wu[k * D_H + n];
        }
    }
}

// ------------------------- k_embed: x = x_in @ W_node + b --------------------
__global__ void __launch_bounds__(256) k_embed(const float* __restrict__ x_in,
                                               const float* __restrict__ W_node,
                                               const float* __restrict__ b_node) {
    __shared__ float sA[64][D_IN + 1];
    __shared__ __align__(16) float sB[D_IN * D_H];
    __shared__ float sb[D_H];
    int tid = threadIdx.x;
    int row0 = blockIdx.x * 64;
    for (int idx = tid; idx < 64 * D_IN; idx += 256) {
        int i = idx >> 5, c = idx & 31;
        int r = row0 + i;
        sA[i][c] = (r < NN) ? x_in[r * D_IN + c] : 0.f;
    }
    for (int idx = tid; idx < D_IN * D_H; idx += 256) sB[idx] = W_node[idx];
    if (tid < D_H) sb[tid] = b_node[tid];
    __syncthreads();
    int tx = tid & 15, ty = tid >> 4;
    float acc[4][8];
#pragma unroll
    for (int r = 0; r < 4; r++)
#pragma unroll
        for (int j = 0; j < 8; j++) acc[r][j] = 0.f;
    for (int c = 0; c < D_IN; c++) {
        float a[4];
#pragma unroll
        for (int r = 0; r < 4; r++) a[r] = sA[ty * 4 + r][c];
        float4 b0 = *(const float4*)(sB + c * D_H + tx * 8);
        float4 b1 = *(const float4*)(sB + c * D_H + tx * 8 + 4);
        float bb[8] = {b0.x, b0.y, b0.z, b0.w, b1.x, b1.y, b1.z, b1.w};
#pragma unroll
        for (int r = 0; r < 4; r++)
#pragma unroll
            for (int j = 0; j < 8; j++) acc[r][j] = fmaf(a[r], bb[j], acc[r][j]);
    }
#pragma unroll
    for (int r = 0; r < 4; r++) {
        int row = row0 + ty * 4 + r;
        if (row < NN) {
#pragma unroll
            for (int j = 0; j < 8; j++) {
                int col = tx * 8 + j;
                g_x[row * D_H + col] = acc[r][j] + sb[col];
            }
        }
    }
}

// ------------------------- k_proj_mma: 64-row tiles, 4 blocks/SM -------------
#define SMEM_PROJ ((64 * 68 + 128 * 68) * 4)
__global__ void __launch_bounds__(256, 4) k_proj_mma(int l) {
    extern __shared__ __align__(16) float sm[];
    float* sA = sm;              // 64 x 68
    float* sB = sm + 64 * 68;    // 128 x 68
    int tid = threadIdx.x;
    int row0 = blockIdx.x * 64;
    int ch = blockIdx.y;
    int wid = tid >> 5, lane = tid & 31;
    int wy = wid >> 2, wx = wid & 3;
    int g = lane >> 2, tig = lane & 3;
    const float* WT = g_WpackT[l][ch];
    float c[2][4][4];
#pragma unroll
    for (int mt = 0; mt < 2; mt++)
#pragma unroll
        for (int nt = 0; nt < 4; nt++)
#pragma unroll
            for (int j = 0; j < 4; j++) c[mt][nt][j] = 0.f;
    for (int chunk = 0; chunk < 2; chunk++) {
        __syncthreads();
        for (int idx = tid; idx < 64 * 16; idx += 256) {
            int m = idx >> 4, q4 = (idx & 15) * 4;
            int r = row0 + m;
            float4 v = make_float4(0.f, 0.f, 0.f, 0.f);
            if (r < NN) v = *(const float4*)(g_x + r * D_H + chunk * 64 + q4);
            v.x = f2tf32(v.x); v.y = f2tf32(v.y); v.z = f2tf32(v.z); v.w = f2tf32(v.w);
            *(float4*)(sA + m * 68 + q4) = v;
        }
        for (int idx = tid; idx < 128 * 16; idx += 256) {
            int n = idx >> 4, q4 = (idx & 15) * 4;
            float4 v = *(const float4*)(WT + n * 128 + chunk * 64 + q4);
            v.x = f2tf32(v.x); v.y = f2tf32(v.y); v.z = f2tf32(v.z); v.w = f2tf32(v.w);
            *(float4*)(sB + n * 68 + q4) = v;
        }
        __syncthreads();
#pragma unroll
        for (int ks = 0; ks < 8; ks++) {
            int ka = ks * 8 + tig;
            uint32_t a[2][4];
#pragma unroll
            for (int mt = 0; mt < 2; mt++) {
                int base = wy * 32 + mt * 16;
                a[mt][0] = __float_as_uint(sA[(base + g) * 68 + ka]);
                a[mt][1] = __float_as_uint(sA[(base + g + 8) * 68 + ka]);
                a[mt][2] = __float_as_uint(sA[(base + g) * 68 + ka + 4]);
                a[mt][3] = __float_as_uint(sA[(base + g + 8) * 68 + ka + 4]);
            }
#pragma unroll
            for (int nt = 0; nt < 4; nt++) {
                int nb = wx * 32 + nt * 8 + g;
                uint32_t b0 = __float_as_uint(sB[nb * 68 + ka]);
                uint32_t b1 = __float_as_uint(sB[nb * 68 + ka + 4]);
                mma8(c[0][nt], a[0], b0, b1);
                mma8(c[1][nt], a[1], b0, b1);
            }
        }
    }
#pragma unroll
    for (int mt = 0; mt < 2; mt++) {
        int r0 = row0 + wy * 32 + mt * 16 + g;
#pragma unroll
        for (int nt = 0; nt < 4; nt++) {
            int col = ch * 128 + wx * 32 + nt * 8 + 2 * tig;
            if (r0 < NN)
                *(float2*)(g_P + (size_t)r0 * PC + col) = make_float2(c[mt][nt][0], c[mt][nt][1]);
            if (r0 + 8 < NN)
                *(float2*)(g_P + (size_t)(r0 + 8) * PC + col) = make_float2(c[mt][nt][2], c[mt][nt][3]);
        }
    }
}

// ------------------------- k_edge: 64-edge tiles, segmented scatter ----------
// smem map (bytes):
// 0 s_dst | 256 s_src | 512 s_et | 768 s_att | 1024 s_ea(2048) | 3072 s_Wf(4096)
// | 7168 s_bf(512) | 7680 s_ba1(256) | 7936 s_wa2(256)
// | 8192 s_hid 64x68 (17408) | 25600 s_B 128x36 (18432) -> 44032 total
#define SMEM_EDGE 44032
__global__ void __launch_bounds__(256, 4) k_edge(
    int l, const int* __restrict__ edge_index, const int* __restrict__ edge_type,
    const float* __restrict__ edge_attr,
    const float* __restrict__ b_leg2, const float* __restrict__ b_eav2,
    const float* __restrict__ W_att2, const float* __restrict__ b_att2,
    const float* __restrict__ b_att1) {
    extern __shared__ __align__(16) char smraw[];
    int* s_dst = (int*)smraw;
    int* s_src = (int*)(smraw + 256);
    int* s_et  = (int*)(smraw + 512);
    float* s_att = (float*)(smraw + 768);
    float* s_ea  = (float*)(smraw + 1024);
    float* s_Wf  = (float*)(smraw + 3072);
    float* s_bf  = (float*)(smraw + 7168);
    float* s_ba1 = (float*)(smraw + 7680);
    float* s_wa2 = (float*)(smraw + 7936);
    float* s_hid = (float*)(smraw + 8192);   // 64 x 68
    float* s_B   = (float*)(smraw + 25600);  // 128 x 36
    float* s_atth = s_hid;                   // gate scratch 64x68 overlay
    __shared__ int sh_np, sh_t0;

    int tid = threadIdx.x;
    int tile0 = blockIdx.x * 64;
    if (tid < 64) {
        int e = g_perm[tile0 + tid];
        s_src[tid] = edge_index[e];
        s_dst[tid] = edge_index[NE + e];
        s_et[tid]  = edge_type[e];
#pragma unroll
        for (int j = 0; j < D_EF; j++) s_ea[tid * D_EF + j] = edge_attr[e * D_EF + j];
    } else if (tid < 128) {
        s_ba1[tid - 64] = b_att1[l * 64 + (tid - 64)];
    } else if (tid < 192) {
        s_wa2[tid - 128] = W_att2[l * 64 + (tid - 128)];
    }
    __syncthreads();
    if (tid == 0) {
        int t0 = s_et[0];
        sh_t0 = t0;
        sh_np = (s_et[63] == t0) ? 1 : 2;
    }
    __syncthreads();
    int npasses = sh_np;
    float ba2 = b_att2[l];
    int wid = tid >> 5, lane = tid & 31;
    int wy = wid >> 2, wx = wid & 3;
    int g = lane >> 2, tig = lane & 3;

    for (int p = 0; p < npasses; p++) {
        int t = (npasses == 1) ? sh_t0 : p;
        // stage folded weights; gate scratch fill
        for (int idx = tid; idx < D_EF * D_H; idx += 256) s_Wf[idx] = g_Wf[l][t][idx];
        if (tid < D_H) s_bf[tid] = g_bf[l][t][tid];
        if (t == 1) {
            for (int idx = tid; idx < 64 * 64; idx += 256) {
                int i = idx >> 6, m = idx & 63;
                int d = s_dst[i], s = s_src[i];
                float v = __ldg(g_P + (size_t)d * PC + 512 + m) +
                          __ldg(g_P + (size_t)s * PC + 576 + m) + s_ba1[m];
                s_atth[m * 68 + i] = fmaxf(v, 0.f);
            }
        }
        __syncthreads();
        if (t == 1) {
            if (tid < 64) {
                float z = ba2;
#pragma unroll 8
                for (int m = 0; m < 64; m++) z = fmaf(s_atth[m * 68 + tid], s_wa2[m], z);
                s_att[tid] = 1.f / (1.f + expf(-z));
            }
            __syncthreads();
        }
        // GEMM accumulators (full 128-N, K accumulated across halves)
        float c[2][4][4];
#pragma unroll
        for (int mt = 0; mt < 2; mt++)
#pragma unroll
            for (int nt = 0; nt < 4; nt++)
#pragma unroll
                for (int j = 0; j < 4; j++) c[mt][nt][j] = 0.f;
        const float* W2T = g_W2T[l][t];
        int cD = t ? 256 : 0;
        for (int h = 0; h < 2; h++) {
            // phase1 for column half h: hidden cols [h*64, h*64+64)
            {
                int q = tid & 15, gi = tid >> 4;
                int k4 = q * 4;
                float4 bf4 = *(const float4*)(s_bf + h * 64 + k4);
#pragma unroll 2
                for (int i = gi; i < 64; i += 16) {
                    int d = s_dst[i], s = s_src[i];
                    float4 vd = __ldg((const float4*)(g_P + (size_t)d * PC + cD + h * 64 + k4));
                    float4 vs = __ldg((const float4*)(g_P + (size_t)s * PC + cD + 128 + h * 64 + k4));
                    float a0 = bf4.x + vd.x + vs.x;
                    float a1 = bf4.y + vd.y + vs.y;
                    float a2v = bf4.z + vd.z + vs.z;
                    float a3 = bf4.w + vd.w + vs.w;
#pragma unroll
                    for (int j = 0; j < D_EF; j++) {
                        float e = s_ea[i * D_EF + j];
                        float4 w = *(const float4*)(s_Wf + j * D_H + h * 64 + k4);
                        a0 = fmaf(e, w.x, a0); a1 = fmaf(e, w.y, a1);
                        a2v = fmaf(e, w.z, a2v); a3 = fmaf(e, w.w, a3);
                    }
                    float* hp = s_hid + i * 68 + k4;
                    *(float2*)hp = make_float2(f2tf32(fmaxf(a0, 0.f)), f2tf32(fmaxf(a1, 0.f)));
                    *(float2*)(hp + 2) = make_float2(f2tf32(fmaxf(a2v, 0.f)), f2tf32(fmaxf(a3, 0.f)));
                }
            }
            __syncthreads();
            for (int chunk = 0; chunk < 2; chunk++) {
                for (int idx = tid; idx < 128 * 8; idx += 256) {
                    int n = idx >> 3, q4 = (idx & 7) * 4;
                    float4 v = *(const float4*)(W2T + n * 128 + h * 64 + chunk * 32 + q4);
                    v.x = f2tf32(v.x); v.y = f2tf32(v.y); v.z = f2tf32(v.z); v.w = f2tf32(v.w);
                    *(float4*)(s_B + n * 36 + q4) = v;
                }
                __syncthreads();
#pragma unroll
                for (int ks = 0; ks < 4; ks++) {
                    int khl = chunk * 32 + ks * 8 + tig;  // local col in s_hid
                    int kb = ks * 8 + tig;
                    uint32_t a[2][4];
#pragma unroll
                    for (int mt = 0; mt < 2; mt++) {
                        int base = wy * 32 + mt * 16;
                        a[mt][0] = __float_as_uint(s_hid[(base + g) * 68 + khl]);
                        a[mt][1] = __float_as_uint(s_hid[(base + g + 8) * 68 + khl]);
                        a[mt][2] = __float_as_uint(s_hid[(base + g) * 68 + khl + 4]);
                        a[mt][3] = __float_as_uint(s_hid[(base + g + 8) * 68 + khl + 4]);
                    }
#pragma unroll
                    for (int nt = 0; nt < 4; nt++) {
                        int nb = wx * 32 + nt * 8 + g;
                        uint32_t b0 = __float_as_uint(s_B[nb * 36 + kb]);
                        uint32_t b1 = __float_as_uint(s_B[nb * 36 + kb + 4]);
                        mma8(c[0][nt], a[0], b0, b1);
                        mma8(c[1][nt], a[1], b0, b1);
                    }
                }
                __syncthreads();
            }
        }
        // epilogue: two output-column halves through s_hid, segmented scatter
        const float* b2 = (t ? b_eav2 : b_leg2) + l * D_H;
        for (int eh = 0; eh < 2; eh++) {
            if ((wx >> 1) == eh) {
#pragma unroll
                for (int mt = 0; mt < 2; mt++) {
                    int i0 = wy * 32 + mt * 16 + g;
                    int i1 = i0 + 8;
                    float sc0 = t ? s_att[i0] : 1.f;
                    float sc1 = t ? s_att[i1] : 1.f;
#pragma unroll
                    for (int nt = 0; nt < 4; nt++) {
                        int colg = wx * 32 + nt * 8 + 2 * tig;
                        int coll = colg - eh * 64;
                        float2 bv = *(const float2*)(b2 + colg);
                        *(float2*)(s_hid + i0 * 68 + coll) =
                            make_float2((c[0 * 0 + mt][nt][0] + bv.x) * sc0,
                                        (c[mt][nt][1] + bv.y) * sc0);
                        *(float2*)(s_hid + i1 * 68 + coll) =
                            make_float2((c[mt][nt][2] + bv.x) * sc1,
                                        (c[mt][nt][3] + bv.y) * sc1);
                    }
                }
            }
            __syncthreads();
            if (tid < 128) {
                int cg = tid & 15, rc = tid >> 4;  // 16 col-groups x 8 row-chunks
                int c4 = cg * 4;
                float ax = 0.f, ay = 0.f, az = 0.f, aw = 0.f;
                int cur = -1;
#pragma unroll
                for (int r = 0; r < 8; r++) {
                    int row = rc * 8 + r;
                    bool ok = (npasses == 1) || (s_et[row] == t);
                    if (!ok) {
                        if (cur >= 0) {
                            red4(g_aggr + (size_t)cur * D_H + eh * 64 + c4, ax, ay, az, aw);
                            cur = -1;
                        }
                        continue;
                    }
                    int d = s_dst[row];
                    if (d != cur) {
                        if (cur >= 0)
                            red4(g_aggr + (size_t)cur * D_H + eh * 64 + c4, ax, ay, az, aw);
                        cur = d;
                        ax = ay = az = aw = 0.f;
                    }
                    float4 v = *(const float4*)(s_hid + row * 68 + c4);
                    ax += v.x; ay += v.y; az += v.z; aw += v.w;
                }
                if (cur >= 0)
                    red4(g_aggr + (size_t)cur * D_H + eh * 64 + c4, ax, ay, az, aw);
            }
            __syncthreads();
        }
    }
}

// ------------------------- k_update_mma: mma + LN + residual -----------------
#define SMEM_UPD ((64 * 68 + 128 * 68 + 128 * 3 + 64 * 4 * 2 + 128) * 4)
__global__ void __launch_bounds__(256, 4) k_update_mma(
    int l, const float* __restrict__ b_upd,
    const float* __restrict__ ln_g, const float* __restrict__ ln_b) {
    extern __shared__ __align__(16) float sm[];
    float* sA = sm;                       // 64 x 68
    float* sB = sA + 64 * 68;             // 128 x 68
    float* sBias = sB + 128 * 68;         // 128
    float* sGam = sBias + 128;            // 128
    float* sBet = sGam + 128;             // 128
    float* sP1 = sBet + 128;              // 64 x 4
    float* sP2 = sP1 + 256;               // 64 x 4
    float* sMu = sP2 + 256;               // 64
    float* sRs = sMu + 64;                // 64
    int tid = threadIdx.x;
    int row0 = blockIdx.x * 64;
    int wid = tid >> 5, lane = tid & 31;
    int wy = wid >> 2, wx = wid & 3;
    int g = lane >> 2, tig = lane & 3;
    if (tid < 128) {
        sBias[tid] = b_upd[l * D_H + tid];
        sGam[tid] = ln_g[l * D_H + tid];
        sBet[tid] = ln_b[l * D_H + tid];
    }
    const float* WuT = g_WuT[l];
    float c[2][4][4];
#pragma unroll
    for (int mt = 0; mt < 2; mt++)
#pragma unroll
        for (int nt = 0; nt < 4; nt++)
#pragma unroll
            for (int j = 0; j < 4; j++) c[mt][nt][j] = 0.f;
    for (int chunk = 0; chunk < 4; chunk++) {
        __syncthreads();
        const float* Asrc = (chunk < 2) ? g_x : g_aggr;
        int cbase = (chunk & 1) * 64;
        for (int idx = tid; idx < 64 * 16; idx += 256) {
            int m = idx >> 4, q4 = (idx & 15) * 4;
            int r = row0 + m;
            float4 v = make_float4(0.f, 0.f, 0.f, 0.f);
            if (r < NN) v = *(const float4*)(Asrc + r * D_H + cbase + q4);
            v.x = f2tf32(v.x); v.y = f2tf32(v.y); v.z = f2tf32(v.z); v.w = f2tf32(v.w);
            *(float4*)(sA + m * 68 + q4) = v;
        }
        for (int idx = tid; idx < 128 * 16; idx += 256) {
            int n = idx >> 4, q4 = (idx & 15) * 4;
            float4 v = *(const float4*)(WuT + n * 256 + chunk * 64 + q4);
            v.x = f2tf32(v.x); v.y = f2tf32(v.y); v.z = f2tf32(v.z); v.w = f2tf32(v.w);
            *(float4*)(sB + n * 68 + q4) = v;
        }
        __syncthreads();
#pragma unroll
        for (int ks = 0; ks < 8; ks++) {
            int ka = ks * 8 + tig;
            uint32_t a[2][4];
#pragma unroll
            for (int mt = 0; mt < 2; mt++) {
                int base = wy * 32 + mt * 16;
                a[mt][0] = __float_as_uint(sA[(base + g) * 68 + ka]);
                a[mt][1] = __float_as_uint(sA[(base + g + 8) * 68 + ka]);
                a[mt][2] = __float_as_uint(sA[(base + g) * 68 + ka + 4]);
                a[mt][3] = __float_as_uint(sA[(base + g + 8) * 68 + ka + 4]);
            }
#pragma unroll
            for (int nt = 0; nt < 4; nt++) {
                int nb = wx * 32 + nt * 8 + g;
                uint32_t b0 = __float_as_uint(sB[nb * 68 + ka]);
                uint32_t b1 = __float_as_uint(sB[nb * 68 + ka + 4]);
                mma8(c[0][nt], a[0], b0, b1);
                mma8(c[1][nt], a[1], b0, b1);
            }
        }
    }
#pragma unroll
    for (int mt = 0; mt < 2; mt++) {
        float s1a = 0.f, s2a = 0.f, s1b = 0.f, s2b = 0.f;
#pragma unroll
        for (int nt = 0; nt < 4; nt++) {
            int col = wx * 32 + nt * 8 + 2 * tig;
            float b0 = sBias[col], b1 = sBias[col + 1];
            c[mt][nt][0] += b0; c[mt][nt][1] += b1;
            c[mt][nt][2] += b0; c[mt][nt][3] += b1;
            s1a += c[mt][nt][0] + c[mt][nt][1];
            s2a += c[mt][nt][0] * c[mt][nt][0] + c[mt][nt][1] * c[mt][nt][1];
            s1b += c[mt][nt][2] + c[mt][nt][3];
            s2b += c[mt][nt][2] * c[mt][nt][2] + c[mt][nt][3] * c[mt][nt][3];
        }
#pragma unroll
        for (int d = 1; d <= 2; d <<= 1) {
            s1a += __shfl_xor_sync(0xffffffff, s1a, d);
            s2a += __shfl_xor_sync(0xffffffff, s2a, d);
            s1b += __shfl_xor_sync(0xffffffff, s1b, d);
            s2b += __shfl_xor_sync(0xffffffff, s2b, d);
        }
        if (tig == 0) {
            int ra = wy * 32 + mt * 16 + g;
            sP1[ra * 4 + wx] = s1a;
            sP2[ra * 4 + wx] = s2a;
            sP1[(ra + 8) * 4 + wx] = s1b;
            sP2[(ra + 8) * 4 + wx] = s2b;
        }
    }
    __syncthreads();
    if (tid < 64) {
        float s1 = sP1[tid * 4] + sP1[tid * 4 + 1] + sP1[tid * 4 + 2] + sP1[tid * 4 + 3];
        float s2 = sP2[tid * 4] + sP2[tid * 4 + 1] + sP2[tid * 4 + 2] + sP2[tid * 4 + 3];
        float mu = s1 * (1.f / D_H);
        float var = fmaxf(s2 * (1.f / D_H) - mu * mu, 0.f);
        sMu[tid] = mu;
        sRs[tid] = rsqrtf(var + LN_EPS);
    }
    __syncthreads();
#pragma unroll
    for (int mt = 0; mt < 2; mt++) {
        int ra = wy * 32 + mt * 16 + g;
        int rows[2] = {ra, ra + 8};
#pragma unroll
        for (int h = 0; h < 2; h++) {
            int rr = rows[h];
            int grow = row0 + rr;
            if (grow >= NN) continue;
            float mu = sMu[rr], rs = sRs[rr];
#pragma unroll
            for (int nt = 0; nt < 4; nt++) {
                int col = wx * 32 + nt * 8 + 2 * tig;
                float v0 = c[mt][nt][h * 2], v1 = c[mt][nt][h * 2 + 1];
                float2 xo = *(const float2*)(g_x + (size_t)grow * D_H + col);
                float h0 = (v0 - mu) * rs * sGam[col] + sBet[col];
                float h1 = (v1 - mu) * rs * sGam[col + 1] + sBet[col + 1];
                float o0 = fmaxf(fmaxf(h0, 0.f) + xo.x, 0.f);
                float o1 = fmaxf(fmaxf(h1, 0.f) + xo.y, 0.f);
                *(float2*)(g_x + (size_t)grow * D_H + col) = make_float2(o0, o1);
            }
        }
    }
}

// ------------------------- k_pool -------------------------------------------
__global__ void k_pool() {
    __shared__ float sp[256];
    int tid = threadIdx.x;
    int row0 = blockIdx.x * 64;
    int k = tid & 127, ih = tid >> 7;
    float v = 0.f;
    for (int i = ih; i < 64; i += 2) {
        int r = row0 + i;
        if (r < NN) v += g_x[r * D_H + k];
    }
    sp[tid] = v;
    __syncthreads();
    if (tid < 128) atomicAdd(&g_pool[k], sp[tid] + sp[tid + 128]);
}

// ------------------------- k_head -------------------------------------------
__global__ void k_head(float* out, const float* __restrict__ traj,
                       const float* __restrict__ W_ref1, const float* __restrict__ b_ref1,
                       const float* __restrict__ W_ref2, const float* __restrict__ b_ref2) {
    __shared__ float sg[D_H], sr1[D_H];
    int tid = threadIdx.x; // 128
    sg[tid] = g_pool[tid] * (1.f / NN);
    __syncthreads();
    float acc = b_ref1[tid];
    for (int c = 0; c < D_H; c++) acc = fmaf(sg[c], W_ref1[c * D_H + tid], acc);
    sr1[tid] = fmaxf(acc, 0.f);
    __syncthreads();
    if (tid < D_OUT) {
        float r2 = b_ref2[tid];
        for (int c = 0; c < D_H; c++) r2 = fmaf(sr1[c], W_ref2[c * D_OUT + tid], r2);
        if (tid < 3) out[164 + tid] = traj[tid] + r2;
    }
    out[167 + tid] = sg[tid];
}

// ------------------------- launch ------------------------------------------
extern "C" void kernel_launch(void* const* d_in, const int* in_sizes, int n_in,
                              void* d_out, int out_size) {
    const float* x_in      = (const float*)d_in[0];
    const float* edge_attr = (const float*)d_in[1];
    const int*   edge_index= (const int*)d_in[2];
    const int*   edge_type = (const int*)d_in[3];
    const float* beam      = (const float*)d_in[5];
    const float* ris       = (const float*)d_in[6];
    const float* traj      = (const float*)d_in[7];
    const float* W_node = (const float*)d_in[8];
    const float* b_node = (const float*)d_in[9];
    const float* W_edge = (const float*)d_in[10];
    const float* b_edge = (const float*)d_in[11];
    const float* W_leg1 = (const float*)d_in[12];
    const float* b_leg1 = (const float*)d_in[13];
    const float* W_leg2 = (const float*)d_in[14];
    const float* b_leg2 = (const float*)d_in[15];
    const float* W_eav1 = (const float*)d_in[16];
    const float* b_eav1 = (const float*)d_in[17];
    const float* W_eav2 = (const float*)d_in[18];
    const float* b_eav2 = (const float*)d_in[19];
    const float* W_att1 = (const float*)d_in[20];
    const float* b_att1 = (const float*)d_in[21];
    const float* W_att2 = (const float*)d_in[22];
    const float* b_att2 = (const float*)d_in[23];
    const float* W_upd  = (const float*)d_in[24];
    const float* b_upd  = (const float*)d_in[25];
    const float* ln_g   = (const float*)d_in[26];
    const float* ln_b   = (const float*)d_in[27];
    const float* W_ref1 = (const float*)d_in[28];
    const float* b_ref1 = (const float*)d_in[29];
    const float* W_ref2 = (const float*)d_in[30];
    const float* b_ref2 = (const float*)d_in[31];
    float* out = (float*)d_out;

    cudaFuncSetAttribute(k_proj_mma,   cudaFuncAttributeMaxDynamicSharedMemorySize, SMEM_PROJ);
    cudaFuncSetAttribute(k_edge,       cudaFuncAttributeMaxDynamicSharedMemorySize, SMEM_EDGE);
    cudaFuncSetAttribute(k_update_mma, cudaFuncAttributeMaxDynamicSharedMemorySize, SMEM_UPD);

    void* aggr_ptr = nullptr;
    void* bins_ptr = nullptr;
    cudaGetSymbolAddress(&aggr_ptr, g_aggr);
    cudaGetSymbolAddress(&bins_ptr, g_bins);

    // edge sort by (type, dst): histogram -> scan -> scatter
    cudaMemsetAsync(bins_ptr, 0, NBPAD * sizeof(int));
    k_hist<<<(NE + 255) / 256, 256>>>(edge_index, edge_type);
    k_scan_local<<<98, 256>>>();
    k_scan_top<<<1, 128>>>();
    k_scan_add<<<98, 256>>>();
    k_scatter<<<(NE + 255) / 256, 256>>>(edge_index, edge_type);

    k_setup<<<21, 256>>>(out, beam, ris, W_leg1, b_leg1, W_eav1, b_eav1,
                         W_edge, b_edge, W_att1, W_leg2, W_eav2, W_upd);
    k_embed<<<NT64, 256>>>(x_in, W_node, b_node);

    for (int l = 0; l < N_L; l++) {
        cudaMemsetAsync(aggr_ptr, 0, (size_t)NN * D_H * sizeof(float));
        k_proj_mma<<<dim3(NT64, 5), 256, SMEM_PROJ>>>(l);
        k_edge<<<NE / 64, 256, SMEM_EDGE>>>(l, edge_index, edge_type, edge_attr,
                                            b_leg2, b_eav2, W_att2, b_att2, b_att1);
        k_update_mma<<<NT64, 256, SMEM_UPD>>>(l, b_upd, ln_g, ln_b);
    }

    k_pool<<<NT64, 256>>>();
    k_head<<<1, 128>>>(out, traj, W_ref1, b_ref1, W_ref2, b_ref2);
}

// round 10
// speedup vs baseline: 1.2018x; 1.1090x over previous
#include <cuda_runtime.h>
#include <cuda_fp16.h>
#include <math.h>
#include <stdint.h>

#define NN 50000
#define NE 400000
#define D_IN 32
#define D_H 128
#define D_EF 8
#define N_L 2
#define D_OUT 16
#define PC 640
#define NT64 ((NN + 63) / 64)
#define LN_EPS 1e-5f

#define NBINS (2 * NN)
#define NBPAD (98 * 1024)

#define LDH 136   // halves per hidden row (128 + 8 pad)
#define LDBH 72   // halves per B row (64 + 8 pad)

// ------------------------- scratch (device globals) -------------------------
__device__ float g_x[NN * D_H];
__device__ float g_aggr[NN * D_H];
__device__ float g_P[NN * PC];
__device__ float g_WpackT[N_L][5][128 * 128]; // [l][ch][n*128 + k]
__device__ __half g_W2h[N_L][2][128 * 128];   // [l][t][n*128 + k] fp16
__device__ float g_WuT[N_L][128 * 256];       // [l][n*256 + k]
__device__ float g_Wf[N_L][2][D_EF * D_H];
__device__ float g_bf[N_L][2][D_H];
__device__ int   g_perm[NE];
__device__ int   g_bins[NBPAD];
__device__ int   g_bsum[98];
__device__ float g_pool[D_H];

// ------------------------- mma helpers ---------------------------------------
__device__ __forceinline__ float f2tf32(float f) {
    uint32_t u;
    asm("cvt.rna.tf32.f32 %0, %1;" : "=r"(u) : "f"(f));
    return __uint_as_float(u);
}
__device__ __forceinline__ void mma8(float* c, const uint32_t* a, uint32_t b0, uint32_t b1) {
    asm volatile(
        "mma.sync.aligned.m16n8k8.row.col.f32.tf32.tf32.f32 "
        "{%0,%1,%2,%3}, {%4,%5,%6,%7}, {%8,%9}, {%0,%1,%2,%3};"
        : "+f"(c[0]), "+f"(c[1]), "+f"(c[2]), "+f"(c[3])
        : "r"(a[0]), "r"(a[1]), "r"(a[2]), "r"(a[3]), "r"(b0), "r"(b1));
}
__device__ __forceinline__ void mma16(float* c, const uint32_t* a, uint32_t b0, uint32_t b1) {
    asm volatile(
        "mma.sync.aligned.m16n8k16.row.col.f32.f16.f16.f32 "
        "{%0,%1,%2,%3}, {%4,%5,%6,%7}, {%8,%9}, {%0,%1,%2,%3};"
        : "+f"(c[0]), "+f"(c[1]), "+f"(c[2]), "+f"(c[3])
        : "r"(a[0]), "r"(a[1]), "r"(a[2]), "r"(a[3]), "r"(b0), "r"(b1));
}
__device__ __forceinline__ void red4(float* p, float x, float y, float z, float w) {
    asm volatile("red.global.add.v4.f32 [%0], {%1,%2,%3,%4};"
                 :: "l"(p), "f"(x), "f"(y), "f"(z), "f"(w) : "memory");
}

// ------------------------- sort kernels --------------------------------------
__global__ void k_hist(const int* __restrict__ edge_index,
                       const int* __restrict__ edge_type) {
    int e = blockIdx.x * blockDim.x + threadIdx.x;
    if (e >= NE) return;
    int bin = edge_type[e] * NN + edge_index[NE + e];
    atomicAdd(&g_bins[bin], 1);
}

__global__ void k_scan_local() {
    __shared__ int sT[256];
    int blk = blockIdx.x, tid = threadIdx.x;
    int base = blk * 1024 + tid * 4;
    int c0 = g_bins[base], c1 = g_bins[base + 1], c2 = g_bins[base + 2], c3 = g_bins[base + 3];
    int tot = c0 + c1 + c2 + c3;
    sT[tid] = tot;
    __syncthreads();
    int v = tot;
#pragma unroll
    for (int d = 1; d < 256; d <<= 1) {
        int u = (tid >= d) ? sT[tid - d] : 0;
        __syncthreads();
        v += u;
        sT[tid] = v;
        __syncthreads();
    }
    int excl = v - tot;
    g_bins[base] = excl;
    g_bins[base + 1] = excl + c0;
    g_bins[base + 2] = excl + c0 + c1;
    g_bins[base + 3] = excl + c0 + c1 + c2;
    if (tid == 255) g_bsum[blk] = v;
}

__global__ void k_scan_top() {
    __shared__ int s[98];
    int tid = threadIdx.x;
    if (tid < 98) s[tid] = g_bsum[tid];
    __syncthreads();
    if (tid == 0) {
        int run = 0;
        for (int i = 0; i < 98; i++) {
            int c = s[i];
            s[i] = run;
            run += c;
        }
    }
    __syncthreads();
    if (tid < 98) g_bsum[tid] = s[tid];
}

__global__ void k_scan_add() {
    int blk = blockIdx.x, tid = threadIdx.x;
    int off = g_bsum[blk];
    int base = blk * 1024 + tid * 4;
    g_bins[base] += off;
    g_bins[base + 1] += off;
    g_bins[base + 2] += off;
    g_bins[base + 3] += off;
}

__global__ void k_scatter(const int* __restrict__ edge_index,
                          const int* __restrict__ edge_type) {
    int e = blockIdx.x * blockDim.x + threadIdx.x;
    if (e >= NE) return;
    int bin = edge_type[e] * NN + edge_index[NE + e];
    int pos = atomicAdd(&g_bins[bin], 1);
    g_perm[pos] = e;
}

// ------------------------- k_setup: zero + fold + packs ----------------------
__global__ void __launch_bounds__(256) k_setup(
    float* out, const float* beam, const float* ris,
    const float* __restrict__ W_leg1, const float* __restrict__ b_leg1,
    const float* __restrict__ W_eav1, const float* __restrict__ b_eav1,
    const float* __restrict__ W_edge, const float* __restrict__ b_edge,
    const float* __restrict__ W_att1,
    const float* __restrict__ W_leg2, const float* __restrict__ W_eav2,
    const float* __restrict__ W_upd) {
    int b = blockIdx.x, tid = threadIdx.x;
    if (b == 0) {
        if (tid < D_H) g_pool[tid] = 0.f;
        if (tid < 64) out[tid] = beam[tid];
        else if (tid < 164) out[tid] = ris[tid - 64];
        return;
    }
    if (b <= 4) {
        __shared__ float sW[64 * D_H];
        __shared__ float sWe[D_EF * D_H];
        __shared__ float sbe[D_H];
        int l = (b - 1) >> 1, t = (b - 1) & 1;
        const float* W1 = (t ? W_eav1 : W_leg1) + l * 384 * D_H;
        const float* b1 = (t ? b_eav1 : b_leg1) + l * D_H;
        for (int idx = tid; idx < D_EF * D_H; idx += 256) sWe[idx] = W_edge[idx];
        if (tid < D_H) sbe[tid] = b_edge[tid];
        float accb = (tid < D_H) ? b1[tid] : 0.f;
        float accj[D_EF];
#pragma unroll
        for (int j = 0; j < D_EF; j++) accj[j] = 0.f;
        for (int cb = 0; cb < 2; cb++) {
            __syncthreads();
            for (int idx = tid; idx < 64 * D_H; idx += 256)
                sW[idx] = W1[(256 + cb * 64 + (idx >> 7)) * D_H + (idx & 127)];
            __syncthreads();
            if (tid < D_H) {
                for (int c2 = 0; c2 < 64; c2++) {
                    float w = sW[c2 * D_H + tid];
                    int c = cb * 64 + c2;
                    accb = fmaf(sbe[c], w, accb);
#pragma unroll
                    for (int j = 0; j < D_EF; j++) accj[j] = fmaf(sWe[j * D_H + c], w, accj[j]);
                }
            }
        }
        if (tid < D_H) {
            g_bf[l][t][tid] = accb;
#pragma unroll
            for (int j = 0; j < D_EF; j++) g_Wf[l][t][j * D_H + tid] = accj[j];
        }
        return;
    }
    if (b <= 14) {
        int l = (b - 5) / 5, ch = (b - 5) % 5;
        for (int idx = tid; idx < 128 * 128; idx += 256) {
            int k = idx >> 7, n = idx & 127;
            float v;
            if (ch < 4) {
                const float* W1 = ((ch >> 1) ? W_eav1 : W_leg1) + l * 384 * D_H;
                v = W1[((ch & 1) * 128 + k) * D_H + n];
            } else {
                const float* Wa = W_att1 + l * 256 * 64;
                v = (n < 64) ? Wa[k * 64 + n] : Wa[(128 + k) * 64 + (n - 64)];
            }
            g_WpackT[l][ch][n * 128 + k] = v;
        }
        return;
    }
    if (b <= 18) {
        int l = (b - 15) >> 1, t = (b - 15) & 1;
        const float* W2 = (t ? W_eav2 : W_leg2) + l * D_H * D_H;
        for (int idx = tid; idx < 128 * 128; idx += 256) {
            int n = idx >> 7, k = idx & 127;
            g_W2h[l][t][n * 128 + k] = __float2half(W2[k * D_H + n]);
        }
        return;
    }
    {
        int l = b - 19;
        const float* Wu = W_upd + l * 256 * D_H;
        for (int idx = tid; idx < 128 * 256; idx += 256) {
            int n = idx >> 8, k = idx & 255;
            g_WuT[l][n * 256 + k] = Wu[k * D_H + n];
        }
    }
}

// ------------------------- k_embed -------------------------------------------
__global__ void __launch_bounds__(256) k_embed(const float* __restrict__ x_in,
                                               const float* __restrict__ W_node,
                                               const float* __restrict__ b_node) {
    __shared__ float sA[64][D_IN + 1];
    __shared__ __align__(16) float sB[D_IN * D_H];
    __shared__ float sb[D_H];
    int tid = threadIdx.x;
    int row0 = blockIdx.x * 64;
    for (int idx = tid; idx < 64 * D_IN; idx += 256) {
        int i = idx >> 5, c = idx & 31;
        int r = row0 + i;
        sA[i][c] = (r < NN) ? x_in[r * D_IN + c] : 0.f;
    }
    for (int idx = tid; idx < D_IN * D_H; idx += 256) sB[idx] = W_node[idx];
    if (tid < D_H) sb[tid] = b_node[tid];
    __syncthreads();
    int tx = tid & 15, ty = tid >> 4;
    float acc[4][8];
#pragma unroll
    for (int r = 0; r < 4; r++)
#pragma unroll
        for (int j = 0; j < 8; j++) acc[r][j] = 0.f;
    for (int c = 0; c < D_IN; c++) {
        float a[4];
#pragma unroll
        for (int r = 0; r < 4; r++) a[r] = sA[ty * 4 + r][c];
        float4 b0 = *(const float4*)(sB + c * D_H + tx * 8);
        float4 b1 = *(const float4*)(sB + c * D_H + tx * 8 + 4);
        float bb[8] = {b0.x, b0.y, b0.z, b0.w, b1.x, b1.y, b1.z, b1.w};
#pragma unroll
        for (int r = 0; r < 4; r++)
#pragma unroll
            for (int j = 0; j < 8; j++) acc[r][j] = fmaf(a[r], bb[j], acc[r][j]);
    }
#pragma unroll
    for (int r = 0; r < 4; r++) {
        int row = row0 + ty * 4 + r;
        if (row < NN) {
#pragma unroll
            for (int j = 0; j < 8; j++) {
                int col = tx * 8 + j;
                g_x[row * D_H + col] = acc[r][j] + sb[col];
            }
        }
    }
}

// ------------------------- k_proj_mma: 64-row tiles, 4 blocks/SM -------------
#define SMEM_PROJ ((64 * 68 + 128 * 68) * 4)
__global__ void __launch_bounds__(256, 4) k_proj_mma(int l) {
    extern __shared__ __align__(16) float sm[];
    float* sA = sm;              // 64 x 68
    float* sB = sm + 64 * 68;    // 128 x 68
    int tid = threadIdx.x;
    int row0 = blockIdx.x * 64;
    int ch = blockIdx.y;
    int wid = tid >> 5, lane = tid & 31;
    int wy = wid >> 2, wx = wid & 3;
    int g = lane >> 2, tig = lane & 3;
    const float* WT = g_WpackT[l][ch];
    float c[2][4][4];
#pragma unroll
    for (int mt = 0; mt < 2; mt++)
#pragma unroll
        for (int nt = 0; nt < 4; nt++)
#pragma unroll
            for (int j = 0; j < 4; j++) c[mt][nt][j] = 0.f;
    for (int chunk = 0; chunk < 2; chunk++) {
        __syncthreads();
        for (int idx = tid; idx < 64 * 16; idx += 256) {
            int m = idx >> 4, q4 = (idx & 15) * 4;
            int r = row0 + m;
            float4 v = make_float4(0.f, 0.f, 0.f, 0.f);
            if (r < NN) v = *(const float4*)(g_x + r * D_H + chunk * 64 + q4);
            v.x = f2tf32(v.x); v.y = f2tf32(v.y); v.z = f2tf32(v.z); v.w = f2tf32(v.w);
            *(float4*)(sA + m * 68 + q4) = v;
        }
        for (int idx = tid; idx < 128 * 16; idx += 256) {
            int n = idx >> 4, q4 = (idx & 15) * 4;
            float4 v = *(const float4*)(WT + n * 128 + chunk * 64 + q4);
            v.x = f2tf32(v.x); v.y = f2tf32(v.y); v.z = f2tf32(v.z); v.w = f2tf32(v.w);
            *(float4*)(sB + n * 68 + q4) = v;
        }
        __syncthreads();
#pragma unroll
        for (int ks = 0; ks < 8; ks++) {
            int ka = ks * 8 + tig;
            uint32_t a[2][4];
#pragma unroll
            for (int mt = 0; mt < 2; mt++) {
                int base = wy * 32 + mt * 16;
                a[mt][0] = __float_as_uint(sA[(base + g) * 68 + ka]);
                a[mt][1] = __float_as_uint(sA[(base + g + 8) * 68 + ka]);
                a[mt][2] = __float_as_uint(sA[(base + g) * 68 + ka + 4]);
                a[mt][3] = __float_as_uint(sA[(base + g + 8) * 68 + ka + 4]);
            }
#pragma unroll
            for (int nt = 0; nt < 4; nt++) {
                int nb = wx * 32 + nt * 8 + g;
                uint32_t b0 = __float_as_uint(sB[nb * 68 + ka]);
                uint32_t b1 = __float_as_uint(sB[nb * 68 + ka + 4]);
                mma8(c[0][nt], a[0], b0, b1);
                mma8(c[1][nt], a[1], b0, b1);
            }
        }
    }
#pragma unroll
    for (int mt = 0; mt < 2; mt++) {
        int r0 = row0 + wy * 32 + mt * 16 + g;
#pragma unroll
        for (int nt = 0; nt < 4; nt++) {
            int col = ch * 128 + wx * 32 + nt * 8 + 2 * tig;
            if (r0 < NN)
                *(float2*)(g_P + (size_t)r0 * PC + col) = make_float2(c[mt][nt][0], c[mt][nt][1]);
            if (r0 + 8 < NN)
                *(float2*)(g_P + (size_t)(r0 + 8) * PC + col) = make_float2(c[mt][nt][2], c[mt][nt][3]);
        }
    }
}

// ------------------------- k_edge: fp16 GEMM2, segmented scatter -------------
// smem map (bytes):
// 0 s_dst | 256 s_src | 512 s_et | 768 s_att | 1024 s_ea(2048) | 3072 s_Wf(4096)
// | 7168 s_bf(512) | 7680 s_ba1(256) | 7936 s_wa2(256)
// | 8192 s_hid half 64xLDH (17408) | 25600 s_Bh half 128xLDBH (18432) -> 44032
#define SMEM_EDGE 44032
__global__ void __launch_bounds__(256, 4) k_edge(
    int l, const int* __restrict__ edge_index, const int* __restrict__ edge_type,
    const float* __restrict__ edge_attr,
    const float* __restrict__ b_leg2, const float* __restrict__ b_eav2,
    const float* __restrict__ W_att2, const float* __restrict__ b_att2,
    const float* __restrict__ b_att1) {
    extern __shared__ __align__(16) char smraw[];
    int* s_dst = (int*)smraw;
    int* s_src = (int*)(smraw + 256);
    int* s_et  = (int*)(smraw + 512);
    float* s_att = (float*)(smraw + 768);
    float* s_ea  = (float*)(smraw + 1024);
    float* s_Wf  = (float*)(smraw + 3072);
    float* s_bf  = (float*)(smraw + 7168);
    float* s_ba1 = (float*)(smraw + 7680);
    float* s_wa2 = (float*)(smraw + 7936);
    __half* s_hid = (__half*)(smraw + 8192);   // 64 x LDH halves
    __half* s_Bh  = (__half*)(smraw + 25600);  // 128 x LDBH halves
    float* s_atth = (float*)(smraw + 8192);    // gate scratch overlay 64x68 f32
    float* s_epi  = (float*)(smraw + 8192);    // epilogue overlay 64x68 f32
    __shared__ int sh_np, sh_t0;

    int tid = threadIdx.x;
    int tile0 = blockIdx.x * 64;
    if (tid < 64) {
        int e = g_perm[tile0 + tid];
        s_src[tid] = edge_index[e];
        s_dst[tid] = edge_index[NE + e];
        s_et[tid]  = edge_type[e];
#pragma unroll
        for (int j = 0; j < D_EF; j++) s_ea[tid * D_EF + j] = edge_attr[e * D_EF + j];
    } else if (tid < 128) {
        s_ba1[tid - 64] = b_att1[l * 64 + (tid - 64)];
    } else if (tid < 192) {
        s_wa2[tid - 128] = W_att2[l * 64 + (tid - 128)];
    }
    __syncthreads();
    if (tid == 0) {
        int t0 = s_et[0];
        sh_t0 = t0;
        sh_np = (s_et[63] == t0) ? 1 : 2;
    }
    __syncthreads();
    int npasses = sh_np;
    float ba2 = b_att2[l];
    int wid = tid >> 5, lane = tid & 31;
    int wy = wid >> 2, wx = wid & 3;
    int g = lane >> 2, tig = lane & 3;

    for (int p = 0; p < npasses; p++) {
        int t = (npasses == 1) ? sh_t0 : p;
        for (int idx = tid; idx < D_EF * D_H; idx += 256) s_Wf[idx] = g_Wf[l][t][idx];
        if (tid < D_H) s_bf[tid] = g_bf[l][t][tid];
        // attention gate (float overlay on hid region)
        if (t == 1) {
            for (int idx = tid; idx < 64 * 64; idx += 256) {
                int i = idx >> 6, m = idx & 63;
                int d = s_dst[i], s = s_src[i];
                float v = __ldg(g_P + (size_t)d * PC + 512 + m) +
                          __ldg(g_P + (size_t)s * PC + 576 + m) + s_ba1[m];
                s_atth[m * 68 + i] = fmaxf(v, 0.f);
            }
            __syncthreads();
            if (tid < 64) {
                float z = ba2;
#pragma unroll 8
                for (int m = 0; m < 64; m++) z = fmaf(s_atth[m * 68 + tid], s_wa2[m], z);
                s_att[tid] = 1.f / (1.f + expf(-z));
            }
        }
        __syncthreads();
        // phase1: hidden = relu(P_dst + P_src + ea@Wf + bf) -> fp16
        {
            int q = tid & 31, gi = tid >> 5;
            int k4 = q * 4;
            int cD = t ? 256 : 0;
            float4 bf4 = *(const float4*)(s_bf + k4);
#pragma unroll 2
            for (int i = gi; i < 64; i += 8) {
                int d = s_dst[i], s = s_src[i];
                float4 vd = __ldg((const float4*)(g_P + (size_t)d * PC + cD + k4));
                float4 vs = __ldg((const float4*)(g_P + (size_t)s * PC + cD + 128 + k4));
                float a0 = bf4.x + vd.x + vs.x;
                float a1 = bf4.y + vd.y + vs.y;
                float a2v = bf4.z + vd.z + vs.z;
                float a3 = bf4.w + vd.w + vs.w;
#pragma unroll
                for (int j = 0; j < D_EF; j++) {
                    float e = s_ea[i * D_EF + j];
                    float4 w = *(const float4*)(s_Wf + j * D_H + k4);
                    a0 = fmaf(e, w.x, a0); a1 = fmaf(e, w.y, a1);
                    a2v = fmaf(e, w.z, a2v); a3 = fmaf(e, w.w, a3);
                }
                __half2* hp = (__half2*)(s_hid + i * LDH + k4);
                hp[0] = __floats2half2_rn(fmaxf(a0, 0.f), fmaxf(a1, 0.f));
                hp[1] = __floats2half2_rn(fmaxf(a2v, 0.f), fmaxf(a3, 0.f));
            }
        }
        __syncthreads();
        // GEMM2: 64x128x128 via fp16 mma (m16n8k16), 64-K B chunks
        const __half* W2h = g_W2h[l][t];
        const float* b2 = (t ? b_eav2 : b_leg2) + l * D_H;
        float c[2][4][4];
#pragma unroll
        for (int mt = 0; mt < 2; mt++)
#pragma unroll
            for (int nt = 0; nt < 4; nt++)
#pragma unroll
                for (int j = 0; j < 4; j++) c[mt][nt][j] = 0.f;
        for (int chunk = 0; chunk < 2; chunk++) {
            // stage B chunk: 128 rows x 64 halves
            for (int idx = tid; idx < 128 * 16; idx += 256) {
                int n = idx >> 4, q4 = (idx & 15) * 4;
                *(uint2*)(s_Bh + n * LDBH + q4) =
                    *(const uint2*)(W2h + n * 128 + chunk * 64 + q4);
            }
            __syncthreads();
#pragma unroll
            for (int ks = 0; ks < 4; ks++) {
                int kh = chunk * 64 + ks * 16;   // global col base in s_hid
                int kb = ks * 16;                // local col base in s_Bh
                uint32_t a[2][4];
#pragma unroll
                for (int mt = 0; mt < 2; mt++) {
                    int base = wy * 32 + mt * 16;
                    a[mt][0] = *(const uint32_t*)(s_hid + (base + g) * LDH + kh + 2 * tig);
                    a[mt][1] = *(const uint32_t*)(s_hid + (base + g + 8) * LDH + kh + 2 * tig);
                    a[mt][2] = *(const uint32_t*)(s_hid + (base + g) * LDH + kh + 8 + 2 * tig);
                    a[mt][3] = *(const uint32_t*)(s_hid + (base + g + 8) * LDH + kh + 8 + 2 * tig);
                }
#pragma unroll
                for (int nt = 0; nt < 4; nt++) {
                    int nb = wx * 32 + nt * 8 + g;
                    uint32_t b0 = *(const uint32_t*)(s_Bh + nb * LDBH + kb + 2 * tig);
                    uint32_t b1 = *(const uint32_t*)(s_Bh + nb * LDBH + kb + 8 + 2 * tig);
                    mma16(c[0][nt], a[0], b0, b1);
                    mma16(c[1][nt], a[1], b0, b1);
                }
            }
            __syncthreads();
        }
        // epilogue: two output-column halves through f32 overlay, segmented scatter
        for (int eh = 0; eh < 2; eh++) {
            if ((wx >> 1) == eh) {
#pragma unroll
                for (int mt = 0; mt < 2; mt++) {
                    int i0 = wy * 32 + mt * 16 + g;
                    int i1 = i0 + 8;
                    float sc0 = t ? s_att[i0] : 1.f;
                    float sc1 = t ? s_att[i1] : 1.f;
#pragma unroll
                    for (int nt = 0; nt < 4; nt++) {
                        int colg = wx * 32 + nt * 8 + 2 * tig;
                        int coll = colg - eh * 64;
                        float2 bv = *(const float2*)(b2 + colg);
                        *(float2*)(s_epi + i0 * 68 + coll) =
                            make_float2((c[mt][nt][0] + bv.x) * sc0,
                                        (c[mt][nt][1] + bv.y) * sc0);
                        *(float2*)(s_epi + i1 * 68 + coll) =
                            make_float2((c[mt][nt][2] + bv.x) * sc1,
                                        (c[mt][nt][3] + bv.y) * sc1);
                    }
                }
            }
            __syncthreads();
            if (tid < 128) {
                int cg = tid & 15, rc = tid >> 4;
                int c4 = cg * 4;
                float ax = 0.f, ay = 0.f, az = 0.f, aw = 0.f;
                int cur = -1;
#pragma unroll
                for (int r = 0; r < 8; r++) {
                    int row = rc * 8 + r;
                    bool ok = (npasses == 1) || (s_et[row] == t);
                    if (!ok) {
                        if (cur >= 0) {
                            red4(g_aggr + (size_t)cur * D_H + eh * 64 + c4, ax, ay, az, aw);
                            cur = -1;
                        }
                        continue;
                    }
                    int d = s_dst[row];
                    if (d != cur) {
                        if (cur >= 0)
                            red4(g_aggr + (size_t)cur * D_H + eh * 64 + c4, ax, ay, az, aw);
                        cur = d;
                        ax = ay = az = aw = 0.f;
                    }
                    float4 v = *(const float4*)(s_epi + row * 68 + c4);
                    ax += v.x; ay += v.y; az += v.z; aw += v.w;
                }
                if (cur >= 0)
                    red4(g_aggr + (size_t)cur * D_H + eh * 64 + c4, ax, ay, az, aw);
            }
            __syncthreads();
        }
    }
}

// ------------------------- k_update_mma: mma + LN + residual -----------------
#define SMEM_UPD ((64 * 68 + 128 * 68 + 128 * 3 + 64 * 4 * 2 + 128) * 4)
__global__ void __launch_bounds__(256, 4) k_update_mma(
    int l, const float* __restrict__ b_upd,
    const float* __restrict__ ln_g, const float* __restrict__ ln_b) {
    extern __shared__ __align__(16) float sm[];
    float* sA = sm;                       // 64 x 68
    float* sB = sA + 64 * 68;             // 128 x 68
    float* sBias = sB + 128 * 68;         // 128
    float* sGam = sBias + 128;            // 128
    float* sBet = sGam + 128;             // 128
    float* sP1 = sBet + 128;              // 64 x 4
    float* sP2 = sP1 + 256;               // 64 x 4
    float* sMu = sP2 + 256;               // 64
    float* sRs = sMu + 64;                // 64
    int tid = threadIdx.x;
    int row0 = blockIdx.x * 64;
    int wid = tid >> 5, lane = tid & 31;
    int wy = wid >> 2, wx = wid & 3;
    int g = lane >> 2, tig = lane & 3;
    if (tid < 128) {
        sBias[tid] = b_upd[l * D_H + tid];
        sGam[tid] = ln_g[l * D_H + tid];
        sBet[tid] = ln_b[l * D_H + tid];
    }
    const float* WuT = g_WuT[l];
    float c[2][4][4];
#pragma unroll
    for (int mt = 0; mt < 2; mt++)
#pragma unroll
        for (int nt = 0; nt < 4; nt++)
#pragma unroll
            for (int j = 0; j < 4; j++) c[mt][nt][j] = 0.f;
    for (int chunk = 0; chunk < 4; chunk++) {
        __syncthreads();
        const float* Asrc = (chunk < 2) ? g_x : g_aggr;
        int cbase = (chunk & 1) * 64;
        for (int idx = tid; idx < 64 * 16; idx += 256) {
            int m = idx >> 4, q4 = (idx & 15) * 4;
            int r = row0 + m;
            float4 v = make_float4(0.f, 0.f, 0.f, 0.f);
            if (r < NN) v = *(const float4*)(Asrc + r * D_H + cbase + q4);
            v.x = f2tf32(v.x); v.y = f2tf32(v.y); v.z = f2tf32(v.z); v.w = f2tf32(v.w);
            *(float4*)(sA + m * 68 + q4) = v;
        }
        for (int idx = tid; idx < 128 * 16; idx += 256) {
            int n = idx >> 4, q4 = (idx & 15) * 4;
            float4 v = *(const float4*)(WuT + n * 256 + chunk * 64 + q4);
            v.x = f2tf32(v.x); v.y = f2tf32(v.y); v.z = f2tf32(v.z); v.w = f2tf32(v.w);
            *(float4*)(sB + n * 68 + q4) = v;
        }
        __syncthreads();
#pragma unroll
        for (int ks = 0; ks < 8; ks++) {
            int ka = ks * 8 + tig;
            uint32_t a[2][4];
#pragma unroll
            for (int mt = 0; mt < 2; mt++) {
                int base = wy * 32 + mt * 16;
                a[mt][0] = __float_as_uint(sA[(base + g) * 68 + ka]);
                a[mt][1] = __float_as_uint(sA[(base + g + 8) * 68 + ka]);
                a[mt][2] = __float_as_uint(sA[(base + g) * 68 + ka + 4]);
                a[mt][3] = __float_as_uint(sA[(base + g + 8) * 68 + ka + 4]);
            }
#pragma unroll
            for (int nt = 0; nt < 4; nt++) {
                int nb = wx * 32 + nt * 8 + g;
                uint32_t b0 = __float_as_uint(sB[nb * 68 + ka]);
                uint32_t b1 = __float_as_uint(sB[nb * 68 + ka + 4]);
                mma8(c[0][nt], a[0], b0, b1);
                mma8(c[1][nt], a[1], b0, b1);
            }
        }
    }
#pragma unroll
    for (int mt = 0; mt < 2; mt++) {
        float s1a = 0.f, s2a = 0.f, s1b = 0.f, s2b = 0.f;
#pragma unroll
        for (int nt = 0; nt < 4; nt++) {
            int col = wx * 32 + nt * 8 + 2 * tig;
            float b0 = sBias[col], b1 = sBias[col + 1];
            c[mt][nt][0] += b0; c[mt][nt][1] += b1;
            c[mt][nt][2] += b0; c[mt][nt][3] += b1;
            s1a += c[mt][nt][0] + c[mt][nt][1];
            s2a += c[mt][nt][0] * c[mt][nt][0] + c[mt][nt][1] * c[mt][nt][1];
            s1b += c[mt][nt][2] + c[mt][nt][3];
            s2b += c[mt][nt][2] * c[mt][nt][2] + c[mt][nt][3] * c[mt][nt][3];
        }
#pragma unroll
        for (int d = 1; d <= 2; d <<= 1) {
            s1a += __shfl_xor_sync(0xffffffff, s1a, d);
            s2a += __shfl_xor_sync(0xffffffff, s2a, d);
            s1b += __shfl_xor_sync(0xffffffff, s1b, d);
            s2b += __shfl_xor_sync(0xffffffff, s2b, d);
        }
        if (tig == 0) {
            int ra = wy * 32 + mt * 16 + g;
            sP1[ra * 4 + wx] = s1a;
            sP2[ra * 4 + wx] = s2a;
            sP1[(ra + 8) * 4 + wx] = s1b;
            sP2[(ra + 8) * 4 + wx] = s2b;
        }
    }
    __syncthreads();
    if (tid < 64) {
        float s1 = sP1[tid * 4] + sP1[tid * 4 + 1] + sP1[tid * 4 + 2] + sP1[tid * 4 + 3];
        float s2 = sP2[tid * 4] + sP2[tid * 4 + 1] + sP2[tid * 4 + 2] + sP2[tid * 4 + 3];
        float mu = s1 * (1.f / D_H);
        float var = fmaxf(s2 * (1.f / D_H) - mu * mu, 0.f);
        sMu[tid] = mu;
        sRs[tid] = rsqrtf(var + LN_EPS);
    }
    __syncthreads();
#pragma unroll
    for (int mt = 0; mt < 2; mt++) {
        int ra = wy * 32 + mt * 16 + g;
        int rows[2] = {ra, ra + 8};
#pragma unroll
        for (int h = 0; h < 2; h++) {
            int rr = rows[h];
            int grow = row0 + rr;
            if (grow >= NN) continue;
            float mu = sMu[rr], rs = sRs[rr];
#pragma unroll
            for (int nt = 0; nt < 4; nt++) {
                int col = wx * 32 + nt * 8 + 2 * tig;
                float v0 = c[mt][nt][h * 2], v1 = c[mt][nt][h * 2 + 1];
                float2 xo = *(const float2*)(g_x + (size_t)grow * D_H + col);
                float h0 = (v0 - mu) * rs * sGam[col] + sBet[col];
                float h1 = (v1 - mu) * rs * sGam[col + 1] + sBet[col + 1];
                float o0 = fmaxf(fmaxf(h0, 0.f) + xo.x, 0.f);
                float o1 = fmaxf(fmaxf(h1, 0.f) + xo.y, 0.f);
                *(float2*)(g_x + (size_t)grow * D_H + col) = make_float2(o0, o1);
            }
        }
    }
}

// ------------------------- k_pool -------------------------------------------
__global__ void k_pool() {
    __shared__ float sp[256];
    int tid = threadIdx.x;
    int row0 = blockIdx.x * 64;
    int k = tid & 127, ih = tid >> 7;
    float v = 0.f;
    for (int i = ih; i < 64; i += 2) {
        int r = row0 + i;
        if (r < NN) v += g_x[r * D_H + k];
    }
    sp[tid] = v;
    __syncthreads();
    if (tid < 128) atomicAdd(&g_pool[k], sp[tid] + sp[tid + 128]);
}

// ------------------------- k_head -------------------------------------------
__global__ void k_head(float* out, const float* __restrict__ traj,
                       const float* __restrict__ W_ref1, const float* __restrict__ b_ref1,
                       const float* __restrict__ W_ref2, const float* __restrict__ b_ref2) {
    __shared__ float sg[D_H], sr1[D_H];
    int tid = threadIdx.x; // 128
    sg[tid] = g_pool[tid] * (1.f / NN);
    __syncthreads();
    float acc = b_ref1[tid];
    for (int c = 0; c < D_H; c++) acc = fmaf(sg[c], W_ref1[c * D_H + tid], acc);
    sr1[tid] = fmaxf(acc, 0.f);
    __syncthreads();
    if (tid < D_OUT) {
        float r2 = b_ref2[tid];
        for (int c = 0; c < D_H; c++) r2 = fmaf(sr1[c], W_ref2[c * D_OUT + tid], r2);
        if (tid < 3) out[164 + tid] = traj[tid] + r2;
    }
    out[167 + tid] = sg[tid];
}

// ------------------------- launch ------------------------------------------
extern "C" void kernel_launch(void* const* d_in, const int* in_sizes, int n_in,
                              void* d_out, int out_size) {
    const float* x_in      = (const float*)d_in[0];
    const float* edge_attr = (const float*)d_in[1];
    const int*   edge_index= (const int*)d_in[2];
    const int*   edge_type = (const int*)d_in[3];
    const float* beam      = (const float*)d_in[5];
    const float* ris       = (const float*)d_in[6];
    const float* traj      = (const float*)d_in[7];
    const float* W_node = (const float*)d_in[8];
    const float* b_node = (const float*)d_in[9];
    const float* W_edge = (const float*)d_in[10];
    const float* b_edge = (const float*)d_in[11];
    const float* W_leg1 = (const float*)d_in[12];
    const float* b_leg1 = (const float*)d_in[13];
    const float* W_leg2 = (const float*)d_in[14];
    const float* b_leg2 = (const float*)d_in[15];
    const float* W_eav1 = (const float*)d_in[16];
    const float* b_eav1 = (const float*)d_in[17];
    const float* W_eav2 = (const float*)d_in[18];
    const float* b_eav2 = (const float*)d_in[19];
    const float* W_att1 = (const float*)d_in[20];
    const float* b_att1 = (const float*)d_in[21];
    const float* W_att2 = (const float*)d_in[22];
    const float* b_att2 = (const float*)d_in[23];
    const float* W_upd  = (const float*)d_in[24];
    const float* b_upd  = (const float*)d_in[25];
    const float* ln_g   = (const float*)d_in[26];
    const float* ln_b   = (const float*)d_in[27];
    const float* W_ref1 = (const float*)d_in[28];
    const float* b_ref1 = (const float*)d_in[29];
    const float* W_ref2 = (const float*)d_in[30];
    const float* b_ref2 = (const float*)d_in[31];
    float* out = (float*)d_out;

    cudaFuncSetAttribute(k_proj_mma,   cudaFuncAttributeMaxDynamicSharedMemorySize, SMEM_PROJ);
    cudaFuncSetAttribute(k_edge,       cudaFuncAttributeMaxDynamicSharedMemorySize, SMEM_EDGE);
    cudaFuncSetAttribute(k_update_mma, cudaFuncAttributeMaxDynamicSharedMemorySize, SMEM_UPD);

    void* aggr_ptr = nullptr;
    void* bins_ptr = nullptr;
    cudaGetSymbolAddress(&aggr_ptr, g_aggr);
    cudaGetSymbolAddress(&bins_ptr, g_bins);

    // edge sort by (type, dst): histogram -> scan -> scatter
    cudaMemsetAsync(bins_ptr, 0, NBPAD * sizeof(int));
    k_hist<<<(NE + 255) / 256, 256>>>(edge_index, edge_type);
    k_scan_local<<<98, 256>>>();
    k_scan_top<<<1, 128>>>();
    k_scan_add<<<98, 256>>>();
    k_scatter<<<(NE + 255) / 256, 256>>>(edge_index, edge_type);

    k_setup<<<21, 256>>>(out, beam, ris, W_leg1, b_leg1, W_eav1, b_eav1,
                         W_edge, b_edge, W_att1, W_leg2, W_eav2, W_upd);
    k_embed<<<NT64, 256>>>(x_in, W_node, b_node);

    for (int l = 0; l < N_L; l++) {
        cudaMemsetAsync(aggr_ptr, 0, (size_t)NN * D_H * sizeof(float));
        k_proj_mma<<<dim3(NT64, 5), 256, SMEM_PROJ>>>(l);
        k_edge<<<NE / 64, 256, SMEM_EDGE>>>(l, edge_index, edge_type, edge_attr,
                                            b_leg2, b_eav2, W_att2, b_att2, b_att1);
        k_update_mma<<<NT64, 256, SMEM_UPD>>>(l, b_upd, ln_g, ln_b);
    }

    k_pool<<<NT64, 256>>>();
    k_head<<<1, 128>>>(out, traj, W_ref1, b_ref1, W_ref2, b_ref2);
}